// round 4
// baseline (speedup 1.0000x reference)
#include <cuda_runtime.h>
#include <cuda_bf16.h>

// Problem constants
#define B_   4
#define S_   2048
#define H_   16
#define DH_  64
#define D_   1024
#define M_   (B_*S_)   // 8192 rows

// ---------------- scratch (device globals: no allocation allowed) ----------
__device__ float g_q[M_ * D_];
__device__ float g_k[M_ * D_];
__device__ float g_v[M_ * D_];
__device__ float g_ctx[M_ * D_];

// ---------------- SGEMM: Y[M,1024] = X[M,1024] @ W[1024,1024] --------------
// 128x128x16 tile, 256 threads, 8x8 micro-tile with interleaved ownership
// rows = ty + 16*i, cols = tx + 16*j  (bank-conflict-free smem reads)
#define TM 128
#define TN 128
#define TK 16

__global__ __launch_bounds__(256, 2)
void gemm1024(const float* __restrict__ X, const float* __restrict__ W,
              float* __restrict__ Y) {
    __shared__ float As[TM * TK];   // As[m][k]  (row-major, stride TK)
    __shared__ float Bs[TK * TN];   // Bs[k][n]  (row-major, stride TN)

    const int tid = threadIdx.x;
    const int tx = tid & 15, ty = tid >> 4;
    const int m0 = blockIdx.y * TM, n0 = blockIdx.x * TN;

    float acc[8][8];
#pragma unroll
    for (int i = 0; i < 8; i++)
#pragma unroll
        for (int j = 0; j < 8; j++) acc[i][j] = 0.f;

    for (int k0 = 0; k0 < 1024; k0 += TK) {
        // A tile: 128x16, each thread loads 8 elems (coalesced 64B rows)
#pragma unroll
        for (int i = 0; i < 8; i++) {
            int idx = tid + i * 256;
            int m = idx >> 4, k = idx & 15;
            As[m * TK + k] = X[(m0 + m) * 1024 + k0 + k];
        }
        // B tile: 16x128 (fully coalesced)
#pragma unroll
        for (int i = 0; i < 8; i++) {
            int idx = tid + i * 256;
            int k = idx >> 7, n = idx & 127;
            Bs[k * TN + n] = W[(k0 + k) * 1024 + n0 + n];
        }
        __syncthreads();

#pragma unroll
        for (int k = 0; k < TK; k++) {
            float a[8], b[8];
#pragma unroll
            for (int i = 0; i < 8; i++) a[i] = As[(ty + 16 * i) * TK + k];
#pragma unroll
            for (int j = 0; j < 8; j++) b[j] = Bs[k * TN + tx + 16 * j];
#pragma unroll
            for (int i = 0; i < 8; i++)
#pragma unroll
                for (int j = 0; j < 8; j++) acc[i][j] += a[i] * b[j];
        }
        __syncthreads();
    }

#pragma unroll
    for (int i = 0; i < 8; i++)
#pragma unroll
        for (int j = 0; j < 8; j++)
            Y[(m0 + ty + 16 * i) * 1024 + n0 + tx + 16 * j] = acc[i][j];
}

// ---------------- Flash attention (fp32, causal + pad mask) ----------------
// One block = (query-tile of 64, head h, batch b). 256 threads.
// Thread (ty,tx) owns score rows ty+16i, cols tx+16j (i,j in 0..3).
#define BR 64
#define BC 64
#define LDSS 65   // smem row stride (conflict-free for strided ownership)

__global__ __launch_bounds__(256, 2)
void flash_attn(const float* __restrict__ q, const float* __restrict__ k,
                const float* __restrict__ v, const int* __restrict__ kini,
                float* __restrict__ ctx) {
    extern __shared__ float smem[];
    float* Qs = smem;                    // 64 x 65
    float* Ks = Qs + BR * LDSS;          // 64 x 65
    float* Vs = Ks + BC * LDSS;          // 64 x 65
    float* Ps = Vs + BC * LDSS;          // 64 x 65
    float* pmask = Ps + BR * LDSS;       // 64

    const int tid = threadIdx.x;
    const int tx = tid & 15, ty = tid >> 4;
    const int qt = blockIdx.x, h = blockIdx.y, b = blockIdx.z;
    const int q0 = qt * BR;
    const int rowbase = b * S_;
    const int hoff = h * DH_;

    // Load Q tile, pre-scaled by 1/sqrt(dh)
    for (int i = tid; i < BR * DH_; i += 256) {
        int r = i >> 6, d = i & 63;
        Qs[r * LDSS + d] = q[(rowbase + q0 + r) * D_ + hoff + d] * 0.125f;
    }

    float m_i[4], l_i[4], o[4][4];
#pragma unroll
    for (int i = 0; i < 4; i++) {
        m_i[i] = -1e30f; l_i[i] = 0.f;
#pragma unroll
        for (int j = 0; j < 4; j++) o[i][j] = 0.f;
    }

    for (int kt = 0; kt <= qt; kt++) {
        const int k0 = kt * BC;
        __syncthreads();  // protect Ks/Vs/Ps reuse (also covers Q load on kt=0)
        for (int i = tid; i < BC * DH_; i += 256) {
            int r = i >> 6, d = i & 63;
            Ks[r * LDSS + d] = k[(rowbase + k0 + r) * D_ + hoff + d];
            Vs[r * LDSS + d] = v[(rowbase + k0 + r) * D_ + hoff + d];
        }
        if (tid < BC)
            pmask[tid] = (kini[rowbase + k0 + tid] != 0) ? 0.f : -1e10f;
        __syncthreads();

        // S = Q K^T  (scaled Q already)
        float s[4][4];
#pragma unroll
        for (int i = 0; i < 4; i++)
#pragma unroll
            for (int j = 0; j < 4; j++) s[i][j] = 0.f;
#pragma unroll 8
        for (int d = 0; d < DH_; d++) {
            float a[4], bb[4];
#pragma unroll
            for (int i = 0; i < 4; i++) a[i] = Qs[(ty + 16 * i) * LDSS + d];
#pragma unroll
            for (int j = 0; j < 4; j++) bb[j] = Ks[(tx + 16 * j) * LDSS + d];
#pragma unroll
            for (int i = 0; i < 4; i++)
#pragma unroll
                for (int j = 0; j < 4; j++) s[i][j] += a[i] * bb[j];
        }

        // masks: subtract 1e10 if pad-masked OR above diagonal (matches ref)
#pragma unroll
        for (int i = 0; i < 4; i++) {
            int gq = q0 + ty + 16 * i;
#pragma unroll
            for (int j = 0; j < 4; j++) {
                int gk = k0 + tx + 16 * j;
                float pen = pmask[tx + 16 * j];
                if (gk > gq) pen = -1e10f;
                s[i][j] += pen;
            }
        }

        // online softmax: row max over 16 lanes (same ty) via butterfly
        float mnew[4], rs[4];
#pragma unroll
        for (int i = 0; i < 4; i++) {
            float rm = s[i][0];
#pragma unroll
            for (int j = 1; j < 4; j++) rm = fmaxf(rm, s[i][j]);
#pragma unroll
            for (int msk = 1; msk < 16; msk <<= 1)
                rm = fmaxf(rm, __shfl_xor_sync(0xffffffffu, rm, msk));
            mnew[i] = fmaxf(m_i[i], rm);
            float r = 0.f;
#pragma unroll
            for (int j = 0; j < 4; j++) {
                float p = __expf(s[i][j] - mnew[i]);
                s[i][j] = p;
                r += p;
            }
#pragma unroll
            for (int msk = 1; msk < 16; msk <<= 1)
                r += __shfl_xor_sync(0xffffffffu, r, msk);
            rs[i] = r;
        }
#pragma unroll
        for (int i = 0; i < 4; i++) {
            float c = __expf(m_i[i] - mnew[i]);
            l_i[i] = l_i[i] * c + rs[i];
            m_i[i] = mnew[i];
#pragma unroll
            for (int j = 0; j < 4; j++) o[i][j] *= c;
        }

        // stage P
#pragma unroll
        for (int i = 0; i < 4; i++)
#pragma unroll
            for (int j = 0; j < 4; j++)
                Ps[(ty + 16 * i) * LDSS + tx + 16 * j] = s[i][j];
        __syncthreads();

        // O += P @ V
#pragma unroll 8
        for (int c = 0; c < BC; c++) {
            float p[4], vv[4];
#pragma unroll
            for (int i = 0; i < 4; i++) p[i] = Ps[(ty + 16 * i) * LDSS + c];
#pragma unroll
            for (int j = 0; j < 4; j++) vv[j] = Vs[c * LDSS + tx + 16 * j];
#pragma unroll
            for (int i = 0; i < 4; i++)
#pragma unroll
                for (int j = 0; j < 4; j++) o[i][j] += p[i] * vv[j];
        }
    }

    // epilogue: normalize and store to ctx[B,S,H,dh] == [M, D] row-major
#pragma unroll
    for (int i = 0; i < 4; i++) {
        float inv = 1.f / l_i[i];
#pragma unroll
        for (int j = 0; j < 4; j++)
            ctx[(rowbase + q0 + ty + 16 * i) * D_ + hoff + tx + 16 * j] =
                o[i][j] * inv;
    }
}

// ---------------- launch -----------------------------------------------------
extern "C" void kernel_launch(void* const* d_in, const int* in_sizes, int n_in,
                              void* d_out, int out_size) {
    const float* Q_emb = (const float*)d_in[0];
    const float* K_emb = (const float*)d_in[1];
    const float* V_emb = (const float*)d_in[2];
    // d_in[3] = Q_ini (unused by reference math)
    const int*   K_ini = (const int*)d_in[4];
    const float* WQ = (const float*)d_in[5];
    const float* WK = (const float*)d_in[6];
    const float* WV = (const float*)d_in[7];
    const float* WO = (const float*)d_in[8];
    float* out = (float*)d_out;

    float *gq, *gk, *gv, *gctx;
    cudaGetSymbolAddress((void**)&gq,   g_q);
    cudaGetSymbolAddress((void**)&gk,   g_k);
    cudaGetSymbolAddress((void**)&gv,   g_v);
    cudaGetSymbolAddress((void**)&gctx, g_ctx);

    const int smem_flash = (4 * BR * LDSS + BC) * (int)sizeof(float);
    cudaFuncSetAttribute(flash_attn, cudaFuncAttributeMaxDynamicSharedMemorySize,
                         smem_flash);

    dim3 ggrid(TN == 128 ? 8 : 8, M_ / TM);  // (1024/128, 8192/128) = (8, 64)

    gemm1024<<<ggrid, 256>>>(Q_emb, WQ, gq);
    gemm1024<<<ggrid, 256>>>(K_emb, WK, gk);
    gemm1024<<<ggrid, 256>>>(V_emb, WV, gv);

    dim3 fgrid(S_ / BR, H_, B_);  // (32, 16, 4)
    flash_attn<<<fgrid, 256, smem_flash>>>(gq, gk, gv, K_ini, gctx);

    gemm1024<<<ggrid, 256>>>(gctx, WO, out);
}

// round 5
// speedup vs baseline: 3.7244x; 3.7244x over previous
#include <cuda_runtime.h>
#include <cuda_bf16.h>
#include <cstdint>

// Problem constants
#define B_   4
#define S_   2048
#define H_   16
#define DH_  64
#define D_   1024
#define M_   (B_*S_)   // 8192 rows

// ---------------- scratch (device globals: no allocation allowed) ----------
__device__ float g_q[M_ * D_];
__device__ float g_k[M_ * D_];
__device__ float g_v[M_ * D_];
__device__ float g_ctx[M_ * D_];

// ---------------- tf32 helpers ---------------------------------------------
__device__ __forceinline__ float to_tf32(float x) {
    float y;
    asm("cvt.rna.tf32.f32 %0, %1;" : "=f"(y) : "f"(x));
    return y;
}

// mma.sync m16n8k8 tf32: D = A(16x8,row) * B(8x8,col) + D
__device__ __forceinline__ void mma_tf32(float c[4], const uint32_t a[4],
                                         uint32_t b0, uint32_t b1) {
    asm volatile(
        "mma.sync.aligned.m16n8k8.row.col.f32.tf32.tf32.f32 "
        "{%0,%1,%2,%3}, {%4,%5,%6,%7}, {%8,%9}, {%0,%1,%2,%3};\n"
        : "+f"(c[0]), "+f"(c[1]), "+f"(c[2]), "+f"(c[3])
        : "r"(a[0]), "r"(a[1]), "r"(a[2]), "r"(a[3]), "r"(b0), "r"(b1));
}

// ---------------- tf32 GEMM: Y[M,1024] = X[M,1024] @ W[1024,1024] ----------
// 128x128 tile, K-chunk 32, 256 threads (8 warps as 4x2), warp = 32x64.
#define LDA 36    // As row stride (128 x 36)  bank: 4g+t4 unique
#define LDB 136   // Bs row stride (32 x 136)  bank: 8t4+g+8n unique

__global__ __launch_bounds__(256, 2)
void gemm_tf32(const float* __restrict__ X, const float* __restrict__ W,
               float* __restrict__ Y) {
    __shared__ float As[128 * LDA];
    __shared__ float Bs[32 * LDB];

    const int tid = threadIdx.x;
    const int lane = tid & 31;
    const int wid = tid >> 5;
    const int g = lane >> 2;    // groupID
    const int t4 = lane & 3;    // threadID_in_group
    const int wm = wid & 3;     // warp row (4 x 32 rows)
    const int wn = wid >> 2;    // warp col (2 x 64 cols)
    const int m0 = blockIdx.y * 128, n0 = blockIdx.x * 128;

    float acc[2][8][4];
#pragma unroll
    for (int am = 0; am < 2; am++)
#pragma unroll
        for (int n = 0; n < 8; n++)
#pragma unroll
            for (int e = 0; e < 4; e++) acc[am][n][e] = 0.f;

    for (int k0 = 0; k0 < 1024; k0 += 32) {
        // A tile 128x32: 1024 float4 loads over 256 threads (4 each)
#pragma unroll
        for (int i = 0; i < 4; i++) {
            int idx = tid + i * 256;            // 0..1023
            int r = idx >> 3, c4 = (idx & 7) * 4;
            float4 t = *(const float4*)&X[(m0 + r) * 1024 + k0 + c4];
            As[r * LDA + c4 + 0] = to_tf32(t.x);
            As[r * LDA + c4 + 1] = to_tf32(t.y);
            As[r * LDA + c4 + 2] = to_tf32(t.z);
            As[r * LDA + c4 + 3] = to_tf32(t.w);
        }
        // B tile 32x128
#pragma unroll
        for (int i = 0; i < 4; i++) {
            int idx = tid + i * 256;
            int r = idx >> 5, c4 = (idx & 31) * 4;
            float4 t = *(const float4*)&W[(k0 + r) * 1024 + n0 + c4];
            Bs[r * LDB + c4 + 0] = to_tf32(t.x);
            Bs[r * LDB + c4 + 1] = to_tf32(t.y);
            Bs[r * LDB + c4 + 2] = to_tf32(t.z);
            Bs[r * LDB + c4 + 3] = to_tf32(t.w);
        }
        __syncthreads();

#pragma unroll
        for (int ks = 0; ks < 4; ks++) {
            const int kk = ks * 8;
            uint32_t a[2][4];
#pragma unroll
            for (int am = 0; am < 2; am++) {
                int rm = wm * 32 + am * 16 + g;
                a[am][0] = __float_as_uint(As[(rm)     * LDA + kk + t4]);
                a[am][1] = __float_as_uint(As[(rm + 8) * LDA + kk + t4]);
                a[am][2] = __float_as_uint(As[(rm)     * LDA + kk + t4 + 4]);
                a[am][3] = __float_as_uint(As[(rm + 8) * LDA + kk + t4 + 4]);
            }
            const int cn = wn * 64;
#pragma unroll
            for (int n = 0; n < 8; n++) {
                uint32_t b0 = __float_as_uint(Bs[(kk + t4)     * LDB + cn + n * 8 + g]);
                uint32_t b1 = __float_as_uint(Bs[(kk + t4 + 4) * LDB + cn + n * 8 + g]);
                mma_tf32(acc[0][n], a[0], b0, b1);
                mma_tf32(acc[1][n], a[1], b0, b1);
            }
        }
        __syncthreads();
    }

    // epilogue: C layout rows (g, g+8), cols 2*t4, 2*t4+1 -> float2 stores
#pragma unroll
    for (int am = 0; am < 2; am++) {
        int r0 = m0 + wm * 32 + am * 16 + g;
#pragma unroll
        for (int n = 0; n < 8; n++) {
            int c = n0 + wn * 64 + n * 8 + 2 * t4;
            *(float2*)&Y[(r0)     * 1024 + c] = make_float2(acc[am][n][0], acc[am][n][1]);
            *(float2*)&Y[(r0 + 8) * 1024 + c] = make_float2(acc[am][n][2], acc[am][n][3]);
        }
    }
}

// ---------------- Flash attention (tf32 MMA, causal + pad mask) ------------
// Block = (q-tile 64, head, batch). 128 threads = 4 warps; warp w owns query
// rows w*16..w*16+15. S and PV both via m16n8k8 tf32.
#define LDQ 68   // Qs/Ks/Ps stride (A frag 4g+t4, K-as-B 4g+t4 : conflict-free)
#define LDV 72   // Vs stride (V-as-B 8t4+g : conflict-free)

__global__ __launch_bounds__(128, 3)
void flash_tf32(const float* __restrict__ q, const float* __restrict__ k,
                const float* __restrict__ v, const int* __restrict__ kini,
                float* __restrict__ ctx) {
    extern __shared__ float smem[];
    float* Qs = smem;                  // 64 x 68
    float* Ks = Qs + 64 * LDQ;         // 64 x 68
    float* Ps = Ks + 64 * LDQ;         // 64 x 68
    float* Vs = Ps + 64 * LDQ;         // 64 x 72
    float* pmask = Vs + 64 * LDV;      // 64

    const int tid = threadIdx.x;
    const int lane = tid & 31;
    const int w = tid >> 5;
    const int g = lane >> 2, t4 = lane & 3;
    const int qt = blockIdx.x, h = blockIdx.y, b = blockIdx.z;
    const int q0 = qt * 64;
    const int rowbase = b * S_;
    const int hoff = h * DH_;

    // Load Q tile (scaled by 1/8, tf32-rounded)
#pragma unroll
    for (int i = 0; i < 8; i++) {
        int idx = tid + i * 128;       // 0..1023
        int r = idx >> 4, c4 = (idx & 15) * 4;
        float4 t = *(const float4*)&q[(rowbase + q0 + r) * D_ + hoff + c4];
        Qs[r * LDQ + c4 + 0] = to_tf32(t.x * 0.125f);
        Qs[r * LDQ + c4 + 1] = to_tf32(t.y * 0.125f);
        Qs[r * LDQ + c4 + 2] = to_tf32(t.z * 0.125f);
        Qs[r * LDQ + c4 + 3] = to_tf32(t.w * 0.125f);
    }

    float m0_ = -1e30f, m1_ = -1e30f, l0_ = 0.f, l1_ = 0.f;
    float o[8][4];
#pragma unroll
    for (int n = 0; n < 8; n++)
#pragma unroll
        for (int e = 0; e < 4; e++) o[n][e] = 0.f;

    const int qbase = w * 16;

    for (int kt = 0; kt <= qt; kt++) {
        const int k0 = kt * 64;
        __syncthreads();   // Ks/Vs safe to overwrite (also orders Qs on kt=0)
#pragma unroll
        for (int i = 0; i < 8; i++) {
            int idx = tid + i * 128;
            int r = idx >> 4, c4 = (idx & 15) * 4;
            float4 tk = *(const float4*)&k[(rowbase + k0 + r) * D_ + hoff + c4];
            Ks[r * LDQ + c4 + 0] = to_tf32(tk.x);
            Ks[r * LDQ + c4 + 1] = to_tf32(tk.y);
            Ks[r * LDQ + c4 + 2] = to_tf32(tk.z);
            Ks[r * LDQ + c4 + 3] = to_tf32(tk.w);
            float4 tv = *(const float4*)&v[(rowbase + k0 + r) * D_ + hoff + c4];
            Vs[r * LDV + c4 + 0] = to_tf32(tv.x);
            Vs[r * LDV + c4 + 1] = to_tf32(tv.y);
            Vs[r * LDV + c4 + 2] = to_tf32(tv.z);
            Vs[r * LDV + c4 + 3] = to_tf32(tv.w);
        }
        if (tid < 64)
            pmask[tid] = (kini[rowbase + k0 + tid] != 0) ? 0.f : -1e10f;
        __syncthreads();

        // ---- S = Q @ K^T : warp rows qbase..qbase+15, all 64 key cols ----
        float s[8][4];
#pragma unroll
        for (int n = 0; n < 8; n++)
#pragma unroll
            for (int e = 0; e < 4; e++) s[n][e] = 0.f;
#pragma unroll
        for (int ks = 0; ks < 8; ks++) {
            const int kk = ks * 8;
            uint32_t a[4];
            a[0] = __float_as_uint(Qs[(qbase + g)     * LDQ + kk + t4]);
            a[1] = __float_as_uint(Qs[(qbase + g + 8) * LDQ + kk + t4]);
            a[2] = __float_as_uint(Qs[(qbase + g)     * LDQ + kk + t4 + 4]);
            a[3] = __float_as_uint(Qs[(qbase + g + 8) * LDQ + kk + t4 + 4]);
#pragma unroll
            for (int n = 0; n < 8; n++) {
                uint32_t b0 = __float_as_uint(Ks[(n * 8 + g) * LDQ + kk + t4]);
                uint32_t b1 = __float_as_uint(Ks[(n * 8 + g) * LDQ + kk + t4 + 4]);
                mma_tf32(s[n], a, b0, b1);
            }
        }

        // ---- masks (pad + causal): single -1e10 penalty, matches ref ----
        const int gq0 = q0 + qbase + g;
        const int gq1 = gq0 + 8;
#pragma unroll
        for (int n = 0; n < 8; n++) {
            int c0 = n * 8 + 2 * t4;
#pragma unroll
            for (int e = 0; e < 2; e++) {
                int gk = k0 + c0 + e;
                float pm = pmask[c0 + e];
                s[n][e]     += (gk > gq0) ? -1e10f : pm;
                s[n][e + 2] += (gk > gq1) ? -1e10f : pm;
            }
        }

        // ---- online softmax (rows gq0 in s[n][0..1], gq1 in s[n][2..3]) --
        float rm0 = -1e30f, rm1 = -1e30f;
#pragma unroll
        for (int n = 0; n < 8; n++) {
            rm0 = fmaxf(rm0, fmaxf(s[n][0], s[n][1]));
            rm1 = fmaxf(rm1, fmaxf(s[n][2], s[n][3]));
        }
#pragma unroll
        for (int msk = 1; msk < 4; msk <<= 1) {
            rm0 = fmaxf(rm0, __shfl_xor_sync(0xffffffffu, rm0, msk));
            rm1 = fmaxf(rm1, __shfl_xor_sync(0xffffffffu, rm1, msk));
        }
        float mn0 = fmaxf(m0_, rm0), mn1 = fmaxf(m1_, rm1);
        float rs0 = 0.f, rs1 = 0.f;
#pragma unroll
        for (int n = 0; n < 8; n++) {
            s[n][0] = __expf(s[n][0] - mn0);
            s[n][1] = __expf(s[n][1] - mn0);
            s[n][2] = __expf(s[n][2] - mn1);
            s[n][3] = __expf(s[n][3] - mn1);
            rs0 += s[n][0] + s[n][1];
            rs1 += s[n][2] + s[n][3];
        }
#pragma unroll
        for (int msk = 1; msk < 4; msk <<= 1) {
            rs0 += __shfl_xor_sync(0xffffffffu, rs0, msk);
            rs1 += __shfl_xor_sync(0xffffffffu, rs1, msk);
        }
        float c0s = __expf(m0_ - mn0), c1s = __expf(m1_ - mn1);
        l0_ = l0_ * c0s + rs0; m0_ = mn0;
        l1_ = l1_ * c1s + rs1; m1_ = mn1;
#pragma unroll
        for (int n = 0; n < 8; n++) {
            o[n][0] *= c0s; o[n][1] *= c0s;
            o[n][2] *= c1s; o[n][3] *= c1s;
        }

        // ---- stage P (tf32) : rows owned exclusively by this warp --------
#pragma unroll
        for (int n = 0; n < 8; n++) {
            int c = n * 8 + 2 * t4;
            Ps[(qbase + g)     * LDQ + c]     = to_tf32(s[n][0]);
            Ps[(qbase + g)     * LDQ + c + 1] = to_tf32(s[n][1]);
            Ps[(qbase + g + 8) * LDQ + c]     = to_tf32(s[n][2]);
            Ps[(qbase + g + 8) * LDQ + c + 1] = to_tf32(s[n][3]);
        }
        __syncwarp();

        // ---- O += P @ V --------------------------------------------------
#pragma unroll
        for (int ks = 0; ks < 8; ks++) {
            const int kk = ks * 8;
            uint32_t a[4];
            a[0] = __float_as_uint(Ps[(qbase + g)     * LDQ + kk + t4]);
            a[1] = __float_as_uint(Ps[(qbase + g + 8) * LDQ + kk + t4]);
            a[2] = __float_as_uint(Ps[(qbase + g)     * LDQ + kk + t4 + 4]);
            a[3] = __float_as_uint(Ps[(qbase + g + 8) * LDQ + kk + t4 + 4]);
#pragma unroll
            for (int n = 0; n < 8; n++) {
                uint32_t b0 = __float_as_uint(Vs[(kk + t4)     * LDV + n * 8 + g]);
                uint32_t b1 = __float_as_uint(Vs[(kk + t4 + 4) * LDV + n * 8 + g]);
                mma_tf32(o[n], a, b0, b1);
            }
        }
        __syncwarp();  // Ps reads done before next iteration overwrites
    }

    // epilogue: normalize, store ctx[M, D] (head slice at hoff)
    float inv0 = 1.f / l0_, inv1 = 1.f / l1_;
    const int r0 = rowbase + q0 + qbase + g;
#pragma unroll
    for (int n = 0; n < 8; n++) {
        int c = hoff + n * 8 + 2 * t4;
        *(float2*)&ctx[(r0)     * D_ + c] = make_float2(o[n][0] * inv0, o[n][1] * inv0);
        *(float2*)&ctx[(r0 + 8) * D_ + c] = make_float2(o[n][2] * inv1, o[n][3] * inv1);
    }
}

// ---------------- launch -----------------------------------------------------
extern "C" void kernel_launch(void* const* d_in, const int* in_sizes, int n_in,
                              void* d_out, int out_size) {
    const float* Q_emb = (const float*)d_in[0];
    const float* K_emb = (const float*)d_in[1];
    const float* V_emb = (const float*)d_in[2];
    // d_in[3] = Q_ini (unused by reference math)
    const int*   K_ini = (const int*)d_in[4];
    const float* WQ = (const float*)d_in[5];
    const float* WK = (const float*)d_in[6];
    const float* WV = (const float*)d_in[7];
    const float* WO = (const float*)d_in[8];
    float* out = (float*)d_out;

    float *gq, *gk, *gv, *gctx;
    cudaGetSymbolAddress((void**)&gq,   g_q);
    cudaGetSymbolAddress((void**)&gk,   g_k);
    cudaGetSymbolAddress((void**)&gv,   g_v);
    cudaGetSymbolAddress((void**)&gctx, g_ctx);

    const int smem_flash = (3 * 64 * LDQ + 64 * LDV + 64) * (int)sizeof(float);
    static bool configured = false;
    cudaFuncSetAttribute(flash_tf32, cudaFuncAttributeMaxDynamicSharedMemorySize,
                         smem_flash);
    (void)configured;

    dim3 ggrid(8, 64);   // (1024/128, 8192/128)
    gemm_tf32<<<ggrid, 256>>>(Q_emb, WQ, gq);
    gemm_tf32<<<ggrid, 256>>>(K_emb, WK, gk);
    gemm_tf32<<<ggrid, 256>>>(V_emb, WV, gv);

    dim3 fgrid(S_ / 64, H_, B_);  // (32, 16, 4)
    flash_tf32<<<fgrid, 128, smem_flash>>>(gq, gk, gv, K_ini, gctx);

    gemm_tf32<<<ggrid, 256>>>(gctx, WO, out);
}

// round 6
// speedup vs baseline: 4.0267x; 1.0812x over previous
#include <cuda_runtime.h>
#include <cuda_bf16.h>
#include <cstdint>

// Problem constants
#define B_   4
#define S_   2048
#define H_   16
#define DH_  64
#define D_   1024
#define M_   (B_*S_)   // 8192 rows

// ---------------- scratch (device globals: no allocation allowed) ----------
__device__ float g_q[M_ * D_];
__device__ float g_k[M_ * D_];
__device__ float g_v[M_ * D_];
__device__ float g_ctx[M_ * D_];

// ---------------- tf32 helpers ---------------------------------------------
__device__ __forceinline__ float to_tf32(float x) {
    float y;
    asm("cvt.rna.tf32.f32 %0, %1;" : "=f"(y) : "f"(x));
    return y;
}

// mma.sync m16n8k8 tf32: D = A(16x8,row) * B(8x8,col) + D
__device__ __forceinline__ void mma_tf32(float c[4], const uint32_t a[4],
                                         uint32_t b0, uint32_t b1) {
    asm volatile(
        "mma.sync.aligned.m16n8k8.row.col.f32.tf32.tf32.f32 "
        "{%0,%1,%2,%3}, {%4,%5,%6,%7}, {%8,%9}, {%0,%1,%2,%3};\n"
        : "+f"(c[0]), "+f"(c[1]), "+f"(c[2]), "+f"(c[3])
        : "r"(a[0]), "r"(a[1]), "r"(a[2]), "r"(a[3]), "r"(b0), "r"(b1));
}

// ---------------- tf32 GEMM: Y[M,1024] = X[M,1024] @ W[1024,1024] ----------
// 128x128 tile, K-chunk 32, 256 threads (8 warps as 4x2), warp = 32x64.
// A-chunk register prefetch; fused z-dim runs up to 3 independent GEMMs.
#define LDA 36    // As row stride
#define LDB 136   // Bs row stride

__global__ __launch_bounds__(256, 2)
void gemm_tf32(const float* __restrict__ X0, const float* __restrict__ X1,
               const float* __restrict__ X2,
               const float* __restrict__ W0, const float* __restrict__ W1,
               const float* __restrict__ W2,
               float* __restrict__ Y0, float* __restrict__ Y1,
               float* __restrict__ Y2) {
    __shared__ float As[128 * LDA];
    __shared__ float Bs[32 * LDB];

    const int z = blockIdx.z;
    const float* X = (z == 0) ? X0 : (z == 1) ? X1 : X2;
    const float* W = (z == 0) ? W0 : (z == 1) ? W1 : W2;
    float*       Y = (z == 0) ? Y0 : (z == 1) ? Y1 : Y2;

    const int tid = threadIdx.x;
    const int lane = tid & 31;
    const int wid = tid >> 5;
    const int g = lane >> 2;
    const int t4 = lane & 3;
    const int wm = wid & 3;
    const int wn = wid >> 2;
    const int m0 = blockIdx.y * 128, n0 = blockIdx.x * 128;

    float acc[2][8][4];
#pragma unroll
    for (int am = 0; am < 2; am++)
#pragma unroll
        for (int n = 0; n < 8; n++)
#pragma unroll
            for (int e = 0; e < 4; e++) acc[am][n][e] = 0.f;

    // prefetch A chunk 0 into registers
    float4 ra[4];
#pragma unroll
    for (int i = 0; i < 4; i++) {
        int idx = tid + i * 256;
        int r = idx >> 3, c4 = (idx & 7) * 4;
        ra[i] = *(const float4*)&X[(m0 + r) * 1024 + c4];
    }

    for (int k0 = 0; k0 < 1024; k0 += 32) {
        // STS A from prefetch regs (tf32-rounded, vectorized)
#pragma unroll
        for (int i = 0; i < 4; i++) {
            int idx = tid + i * 256;
            int r = idx >> 3, c4 = (idx & 7) * 4;
            *(float4*)&As[r * LDA + c4] =
                make_float4(to_tf32(ra[i].x), to_tf32(ra[i].y),
                            to_tf32(ra[i].z), to_tf32(ra[i].w));
        }
        // B tile 32x128 (W is L2-resident: load inline)
#pragma unroll
        for (int i = 0; i < 4; i++) {
            int idx = tid + i * 256;
            int r = idx >> 5, c4 = (idx & 31) * 4;
            float4 t = *(const float4*)&W[(k0 + r) * 1024 + n0 + c4];
            *(float4*)&Bs[r * LDB + c4] =
                make_float4(to_tf32(t.x), to_tf32(t.y),
                            to_tf32(t.z), to_tf32(t.w));
        }
        __syncthreads();

        // issue next A-chunk LDGs early (overlap DRAM latency with MMA)
        if (k0 + 32 < 1024) {
#pragma unroll
            for (int i = 0; i < 4; i++) {
                int idx = tid + i * 256;
                int r = idx >> 3, c4 = (idx & 7) * 4;
                ra[i] = *(const float4*)&X[(m0 + r) * 1024 + k0 + 32 + c4];
            }
        }

#pragma unroll
        for (int ks = 0; ks < 4; ks++) {
            const int kk = ks * 8;
            uint32_t a[2][4];
#pragma unroll
            for (int am = 0; am < 2; am++) {
                int rm = wm * 32 + am * 16 + g;
                a[am][0] = __float_as_uint(As[(rm)     * LDA + kk + t4]);
                a[am][1] = __float_as_uint(As[(rm + 8) * LDA + kk + t4]);
                a[am][2] = __float_as_uint(As[(rm)     * LDA + kk + t4 + 4]);
                a[am][3] = __float_as_uint(As[(rm + 8) * LDA + kk + t4 + 4]);
            }
            const int cn = wn * 64;
#pragma unroll
            for (int n = 0; n < 8; n++) {
                uint32_t b0 = __float_as_uint(Bs[(kk + t4)     * LDB + cn + n * 8 + g]);
                uint32_t b1 = __float_as_uint(Bs[(kk + t4 + 4) * LDB + cn + n * 8 + g]);
                mma_tf32(acc[0][n], a[0], b0, b1);
                mma_tf32(acc[1][n], a[1], b0, b1);
            }
        }
        __syncthreads();
    }

#pragma unroll
    for (int am = 0; am < 2; am++) {
        int r0 = m0 + wm * 32 + am * 16 + g;
#pragma unroll
        for (int n = 0; n < 8; n++) {
            int c = n0 + wn * 64 + n * 8 + 2 * t4;
            *(float2*)&Y[(r0)     * 1024 + c] = make_float2(acc[am][n][0], acc[am][n][1]);
            *(float2*)&Y[(r0 + 8) * 1024 + c] = make_float2(acc[am][n][2], acc[am][n][3]);
        }
    }
}

// ---------------- Flash attention (tf32 MMA, causal + pad mask) ------------
// Block = (q-tile 128, head, batch). 128 threads = 4 warps; warp w owns query
// rows w*32..w*32+31 as two m16 sub-tiles (K/V fragments shared across both).
#define BRF 128
#define BCF 64
#define LDQ 68   // Qs/Ks/Ps stride (4g+t4 : conflict-free)
#define LDV 72   // Vs stride (8t4+g : conflict-free)

__global__ __launch_bounds__(128, 2)
void flash_tf32(const float* __restrict__ q, const float* __restrict__ k,
                const float* __restrict__ v, const int* __restrict__ kini,
                float* __restrict__ ctx) {
    extern __shared__ float smem[];
    float* Qs = smem;                   // 128 x 68
    float* Ks = Qs + BRF * LDQ;         // 64 x 68
    float* Ps = Ks + BCF * LDQ;         // 128 x 68
    float* Vs = Ps + BRF * LDQ;         // 64 x 72
    float* pmask = Vs + BCF * LDV;      // 64

    const int tid = threadIdx.x;
    const int lane = tid & 31;
    const int w = tid >> 5;
    const int g = lane >> 2, t4 = lane & 3;
    const int qt = blockIdx.x, h = blockIdx.y, b = blockIdx.z;
    const int q0 = qt * BRF;
    const int rowbase = b * S_;
    const int hoff = h * DH_;

    // Load Q tile 128x64 (scaled by 1/8, tf32-rounded, STS.128)
#pragma unroll
    for (int i = 0; i < 16; i++) {
        int idx = tid + i * 128;        // 0..2047 float4s
        int r = idx >> 4, c4 = (idx & 15) * 4;
        float4 t = *(const float4*)&q[(rowbase + q0 + r) * D_ + hoff + c4];
        *(float4*)&Qs[r * LDQ + c4] =
            make_float4(to_tf32(t.x * 0.125f), to_tf32(t.y * 0.125f),
                        to_tf32(t.z * 0.125f), to_tf32(t.w * 0.125f));
    }

    float m_[2][2], l_[2][2];
    float o[2][8][4];
#pragma unroll
    for (int am = 0; am < 2; am++) {
        m_[am][0] = -1e30f; m_[am][1] = -1e30f;
        l_[am][0] = 0.f;    l_[am][1] = 0.f;
#pragma unroll
        for (int n = 0; n < 8; n++)
#pragma unroll
            for (int e = 0; e < 4; e++) o[am][n][e] = 0.f;
    }

    const int qb = w * 32;
    const int ktmax = 2 * qt + 1;

    for (int kt = 0; kt <= ktmax; kt++) {
        const int k0 = kt * BCF;
        __syncthreads();   // Ks/Vs safe to overwrite (also orders Qs on kt=0)
#pragma unroll
        for (int i = 0; i < 8; i++) {
            int idx = tid + i * 128;    // 0..1023 float4s
            int r = idx >> 4, c4 = (idx & 15) * 4;
            float4 tk = *(const float4*)&k[(rowbase + k0 + r) * D_ + hoff + c4];
            *(float4*)&Ks[r * LDQ + c4] =
                make_float4(to_tf32(tk.x), to_tf32(tk.y), to_tf32(tk.z), to_tf32(tk.w));
            float4 tv = *(const float4*)&v[(rowbase + k0 + r) * D_ + hoff + c4];
            *(float4*)&Vs[r * LDV + c4] =
                make_float4(to_tf32(tv.x), to_tf32(tv.y), to_tf32(tv.z), to_tf32(tv.w));
        }
        if (tid < 64)
            pmask[tid] = (kini[rowbase + k0 + tid] != 0) ? 0.f : -1e10f;
        __syncthreads();

        // ---- S = Q @ K^T : 32 warp rows x 64 key cols --------------------
        float s[2][8][4];
#pragma unroll
        for (int am = 0; am < 2; am++)
#pragma unroll
            for (int n = 0; n < 8; n++)
#pragma unroll
                for (int e = 0; e < 4; e++) s[am][n][e] = 0.f;
#pragma unroll
        for (int ks = 0; ks < 8; ks++) {
            const int kk = ks * 8;
            uint32_t a[2][4];
#pragma unroll
            for (int am = 0; am < 2; am++) {
                int rq = qb + am * 16 + g;
                a[am][0] = __float_as_uint(Qs[(rq)     * LDQ + kk + t4]);
                a[am][1] = __float_as_uint(Qs[(rq + 8) * LDQ + kk + t4]);
                a[am][2] = __float_as_uint(Qs[(rq)     * LDQ + kk + t4 + 4]);
                a[am][3] = __float_as_uint(Qs[(rq + 8) * LDQ + kk + t4 + 4]);
            }
#pragma unroll
            for (int n = 0; n < 8; n++) {
                uint32_t b0 = __float_as_uint(Ks[(n * 8 + g) * LDQ + kk + t4]);
                uint32_t b1 = __float_as_uint(Ks[(n * 8 + g) * LDQ + kk + t4 + 4]);
                mma_tf32(s[0][n], a[0], b0, b1);
                mma_tf32(s[1][n], a[1], b0, b1);
            }
        }

        // ---- masks + online softmax per am block -------------------------
#pragma unroll
        for (int am = 0; am < 2; am++) {
            const int gq0 = q0 + qb + am * 16 + g;
            const int gq1 = gq0 + 8;
#pragma unroll
            for (int n = 0; n < 8; n++) {
                int c0 = n * 8 + 2 * t4;
#pragma unroll
                for (int e = 0; e < 2; e++) {
                    int gk = k0 + c0 + e;
                    float pm = pmask[c0 + e];
                    s[am][n][e]     += (gk > gq0) ? -1e10f : pm;
                    s[am][n][e + 2] += (gk > gq1) ? -1e10f : pm;
                }
            }
            float rm0 = -1e30f, rm1 = -1e30f;
#pragma unroll
            for (int n = 0; n < 8; n++) {
                rm0 = fmaxf(rm0, fmaxf(s[am][n][0], s[am][n][1]));
                rm1 = fmaxf(rm1, fmaxf(s[am][n][2], s[am][n][3]));
            }
#pragma unroll
            for (int msk = 1; msk < 4; msk <<= 1) {
                rm0 = fmaxf(rm0, __shfl_xor_sync(0xffffffffu, rm0, msk));
                rm1 = fmaxf(rm1, __shfl_xor_sync(0xffffffffu, rm1, msk));
            }
            float mn0 = fmaxf(m_[am][0], rm0), mn1 = fmaxf(m_[am][1], rm1);
            float rs0 = 0.f, rs1 = 0.f;
#pragma unroll
            for (int n = 0; n < 8; n++) {
                s[am][n][0] = __expf(s[am][n][0] - mn0);
                s[am][n][1] = __expf(s[am][n][1] - mn0);
                s[am][n][2] = __expf(s[am][n][2] - mn1);
                s[am][n][3] = __expf(s[am][n][3] - mn1);
                rs0 += s[am][n][0] + s[am][n][1];
                rs1 += s[am][n][2] + s[am][n][3];
            }
#pragma unroll
            for (int msk = 1; msk < 4; msk <<= 1) {
                rs0 += __shfl_xor_sync(0xffffffffu, rs0, msk);
                rs1 += __shfl_xor_sync(0xffffffffu, rs1, msk);
            }
            float c0s = __expf(m_[am][0] - mn0), c1s = __expf(m_[am][1] - mn1);
            l_[am][0] = l_[am][0] * c0s + rs0; m_[am][0] = mn0;
            l_[am][1] = l_[am][1] * c1s + rs1; m_[am][1] = mn1;
#pragma unroll
            for (int n = 0; n < 8; n++) {
                o[am][n][0] *= c0s; o[am][n][1] *= c0s;
                o[am][n][2] *= c1s; o[am][n][3] *= c1s;
            }

            // stage P (tf32, float2 stores; rows owned exclusively by warp)
            const int rq = qb + am * 16 + g;
#pragma unroll
            for (int n = 0; n < 8; n++) {
                int c = n * 8 + 2 * t4;
                *(float2*)&Ps[(rq)     * LDQ + c] =
                    make_float2(to_tf32(s[am][n][0]), to_tf32(s[am][n][1]));
                *(float2*)&Ps[(rq + 8) * LDQ + c] =
                    make_float2(to_tf32(s[am][n][2]), to_tf32(s[am][n][3]));
            }
        }
        __syncwarp();

        // ---- O += P @ V (V fragments shared across both am blocks) -------
#pragma unroll
        for (int ks = 0; ks < 8; ks++) {
            const int kk = ks * 8;
            uint32_t a[2][4];
#pragma unroll
            for (int am = 0; am < 2; am++) {
                int rq = qb + am * 16 + g;
                a[am][0] = __float_as_uint(Ps[(rq)     * LDQ + kk + t4]);
                a[am][1] = __float_as_uint(Ps[(rq + 8) * LDQ + kk + t4]);
                a[am][2] = __float_as_uint(Ps[(rq)     * LDQ + kk + t4 + 4]);
                a[am][3] = __float_as_uint(Ps[(rq + 8) * LDQ + kk + t4 + 4]);
            }
#pragma unroll
            for (int n = 0; n < 8; n++) {
                uint32_t b0 = __float_as_uint(Vs[(kk + t4)     * LDV + n * 8 + g]);
                uint32_t b1 = __float_as_uint(Vs[(kk + t4 + 4) * LDV + n * 8 + g]);
                mma_tf32(o[0][n], a[0], b0, b1);
                mma_tf32(o[1][n], a[1], b0, b1);
            }
        }
        __syncwarp();  // Ps reads done before next iteration overwrites
    }

    // epilogue: normalize, store ctx[M, D] (head slice at hoff)
#pragma unroll
    for (int am = 0; am < 2; am++) {
        float inv0 = 1.f / l_[am][0], inv1 = 1.f / l_[am][1];
        const int r0 = rowbase + q0 + qb + am * 16 + g;
#pragma unroll
        for (int n = 0; n < 8; n++) {
            int c = hoff + n * 8 + 2 * t4;
            *(float2*)&ctx[(r0)     * D_ + c] =
                make_float2(o[am][n][0] * inv0, o[am][n][1] * inv0);
            *(float2*)&ctx[(r0 + 8) * D_ + c] =
                make_float2(o[am][n][2] * inv1, o[am][n][3] * inv1);
        }
    }
}

// ---------------- launch -----------------------------------------------------
extern "C" void kernel_launch(void* const* d_in, const int* in_sizes, int n_in,
                              void* d_out, int out_size) {
    const float* Q_emb = (const float*)d_in[0];
    const float* K_emb = (const float*)d_in[1];
    const float* V_emb = (const float*)d_in[2];
    // d_in[3] = Q_ini (unused by reference math)
    const int*   K_ini = (const int*)d_in[4];
    const float* WQ = (const float*)d_in[5];
    const float* WK = (const float*)d_in[6];
    const float* WV = (const float*)d_in[7];
    const float* WO = (const float*)d_in[8];
    float* out = (float*)d_out;

    float *gq, *gk, *gv, *gctx;
    cudaGetSymbolAddress((void**)&gq,   g_q);
    cudaGetSymbolAddress((void**)&gk,   g_k);
    cudaGetSymbolAddress((void**)&gv,   g_v);
    cudaGetSymbolAddress((void**)&gctx, g_ctx);

    const int smem_flash =
        (BRF * LDQ + BCF * LDQ + BRF * LDQ + BCF * LDV + 64) * (int)sizeof(float);
    cudaFuncSetAttribute(flash_tf32, cudaFuncAttributeMaxDynamicSharedMemorySize,
                         smem_flash);

    // fused QKV projections: grid.z = 3
    dim3 ggrid3(8, 64, 3);
    gemm_tf32<<<ggrid3, 256>>>(Q_emb, K_emb, V_emb, WQ, WK, WV, gq, gk, gv);

    dim3 fgrid(S_ / BRF, H_, B_);  // (16, 16, 4)
    flash_tf32<<<fgrid, 128, smem_flash>>>(gq, gk, gv, K_ini, gctx);

    // output projection: grid.z = 1
    dim3 ggrid1(8, 64, 1);
    gemm_tf32<<<ggrid1, 256>>>(gctx, gctx, gctx, WO, WO, WO, out, out, out);
}

// round 8
// speedup vs baseline: 4.1413x; 1.0285x over previous
#include <cuda_runtime.h>
#include <cuda_bf16.h>
#include <cstdint>

// Problem constants
#define B_   4
#define S_   2048
#define H_   16
#define DH_  64
#define D_   1024
#define M_   (B_*S_)   // 8192 rows

// ---------------- scratch (device globals: no allocation allowed) ----------
__device__ float g_q[M_ * D_];
__device__ float g_k[M_ * D_];
__device__ float g_v[M_ * D_];
__device__ float g_ctx[M_ * D_];

// ---------------- tf32 helpers ---------------------------------------------
__device__ __forceinline__ float to_tf32(float x) {
    float y;
    asm("cvt.rna.tf32.f32 %0, %1;" : "=f"(y) : "f"(x));
    return y;
}

// mma.sync m16n8k8 tf32: D = A(16x8,row) * B(8x8,col) + D
__device__ __forceinline__ void mma_tf32(float c[4], const uint32_t a[4],
                                         uint32_t b0, uint32_t b1) {
    asm volatile(
        "mma.sync.aligned.m16n8k8.row.col.f32.tf32.tf32.f32 "
        "{%0,%1,%2,%3}, {%4,%5,%6,%7}, {%8,%9}, {%0,%1,%2,%3};\n"
        : "+f"(c[0]), "+f"(c[1]), "+f"(c[2]), "+f"(c[3])
        : "r"(a[0]), "r"(a[1]), "r"(a[2]), "r"(a[3]), "r"(b0), "r"(b1));
}

// ---------------- tf32 GEMM: Y[M,1024] = X[M,1024] @ W[1024,1024] ----------
// 128x128 tile, K-chunk 16, DOUBLE-BUFFERED smem, 256 threads (8 warps 4x2),
// warp = 32x64. One __syncthreads per chunk; fill overlaps compute.
#define LDA 20    // As row stride (k16): fragment banks 4g+t4 conflict-free
#define LDB 136   // Bs row stride
#define ASZ (128 * LDA)   // 2560 floats
#define BSZ (16 * LDB)    // 2176 floats
#define NCH 64            // 1024 / 16 chunks

__global__ __launch_bounds__(256, 2)
void gemm_tf32(const float* __restrict__ X0, const float* __restrict__ X1,
               const float* __restrict__ X2,
               const float* __restrict__ W0, const float* __restrict__ W1,
               const float* __restrict__ W2,
               float* __restrict__ Y0, float* __restrict__ Y1,
               float* __restrict__ Y2) {
    __shared__ float As[2 * ASZ];
    __shared__ float Bs[2 * BSZ];

    const int z = blockIdx.z;
    const float* X = (z == 0) ? X0 : (z == 1) ? X1 : X2;
    const float* W = (z == 0) ? W0 : (z == 1) ? W1 : W2;
    float*       Y = (z == 0) ? Y0 : (z == 1) ? Y1 : Y2;

    const int tid = threadIdx.x;
    const int lane = tid & 31;
    const int wid = tid >> 5;
    const int g = lane >> 2;
    const int t4 = lane & 3;
    const int wm = wid & 3;
    const int wn = wid >> 2;
    const int m0 = blockIdx.y * 128, n0 = blockIdx.x * 128;

    // fill coordinates (2 float4 per thread per matrix per chunk)
    const int ar0 = tid >> 2,          ac0 = (tid & 3) * 4;          // A idx=tid
    const int ar1 = (tid + 256) >> 2,  ac1 = ((tid + 256) & 3) * 4;  // A idx=tid+256
    const int br0 = tid >> 5,          bc0 = (tid & 31) * 4;
    const int br1 = (tid + 256) >> 5,  bc1 = ((tid + 256) & 31) * 4;

    float acc[2][8][4];
#pragma unroll
    for (int am = 0; am < 2; am++)
#pragma unroll
        for (int n = 0; n < 8; n++)
#pragma unroll
            for (int e = 0; e < 4; e++) acc[am][n][e] = 0.f;

    float4 ra0, ra1, rb0, rb1;

    // ---- prologue: LDG chunk0 -> STS buf0 -> LDG chunk1 -> sync ----
    ra0 = *(const float4*)&X[(m0 + ar0) * 1024 + ac0];
    ra1 = *(const float4*)&X[(m0 + ar1) * 1024 + ac1];
    rb0 = *(const float4*)&W[(br0) * 1024 + n0 + bc0];
    rb1 = *(const float4*)&W[(br1) * 1024 + n0 + bc1];

    *(float4*)&As[ar0 * LDA + ac0] = make_float4(to_tf32(ra0.x), to_tf32(ra0.y),
                                                 to_tf32(ra0.z), to_tf32(ra0.w));
    *(float4*)&As[ar1 * LDA + ac1] = make_float4(to_tf32(ra1.x), to_tf32(ra1.y),
                                                 to_tf32(ra1.z), to_tf32(ra1.w));
    *(float4*)&Bs[br0 * LDB + bc0] = make_float4(to_tf32(rb0.x), to_tf32(rb0.y),
                                                 to_tf32(rb0.z), to_tf32(rb0.w));
    *(float4*)&Bs[br1 * LDB + bc1] = make_float4(to_tf32(rb1.x), to_tf32(rb1.y),
                                                 to_tf32(rb1.z), to_tf32(rb1.w));

    ra0 = *(const float4*)&X[(m0 + ar0) * 1024 + 16 + ac0];
    ra1 = *(const float4*)&X[(m0 + ar1) * 1024 + 16 + ac1];
    rb0 = *(const float4*)&W[(16 + br0) * 1024 + n0 + bc0];
    rb1 = *(const float4*)&W[(16 + br1) * 1024 + n0 + bc1];
    __syncthreads();

    for (int kc = 0; kc < NCH; kc++) {
        const float* Ab = As + (kc & 1) * ASZ;
        const float* Bb = Bs + (kc & 1) * BSZ;

        // ---- compute chunk kc (2 k8 steps, 32 MMAs/warp) ----
#pragma unroll
        for (int ks = 0; ks < 2; ks++) {
            const int kk = ks * 8;
            uint32_t a[2][4];
#pragma unroll
            for (int am = 0; am < 2; am++) {
                int rm = wm * 32 + am * 16 + g;
                a[am][0] = __float_as_uint(Ab[(rm)     * LDA + kk + t4]);
                a[am][1] = __float_as_uint(Ab[(rm + 8) * LDA + kk + t4]);
                a[am][2] = __float_as_uint(Ab[(rm)     * LDA + kk + t4 + 4]);
                a[am][3] = __float_as_uint(Ab[(rm + 8) * LDA + kk + t4 + 4]);
            }
            const int cn = wn * 64;
#pragma unroll
            for (int n = 0; n < 8; n++) {
                uint32_t b0 = __float_as_uint(Bb[(kk + t4)     * LDB + cn + n * 8 + g]);
                uint32_t b1 = __float_as_uint(Bb[(kk + t4 + 4) * LDB + cn + n * 8 + g]);
                mma_tf32(acc[0][n], a[0], b0, b1);
                mma_tf32(acc[1][n], a[1], b0, b1);
            }
        }

        // ---- STS chunk kc+1 into other buffer (regs already resident) ----
        if (kc + 1 < NCH) {
            float* An = As + ((kc + 1) & 1) * ASZ;
            float* Bn = Bs + ((kc + 1) & 1) * BSZ;
            *(float4*)&An[ar0 * LDA + ac0] =
                make_float4(to_tf32(ra0.x), to_tf32(ra0.y), to_tf32(ra0.z), to_tf32(ra0.w));
            *(float4*)&An[ar1 * LDA + ac1] =
                make_float4(to_tf32(ra1.x), to_tf32(ra1.y), to_tf32(ra1.z), to_tf32(ra1.w));
            *(float4*)&Bn[br0 * LDB + bc0] =
                make_float4(to_tf32(rb0.x), to_tf32(rb0.y), to_tf32(rb0.z), to_tf32(rb0.w));
            *(float4*)&Bn[br1 * LDB + bc1] =
                make_float4(to_tf32(rb1.x), to_tf32(rb1.y), to_tf32(rb1.z), to_tf32(rb1.w));
        }
        // ---- LDG chunk kc+2 (arrives during compute of kc+1) ----
        if (kc + 2 < NCH) {
            const int ko = (kc + 2) * 16;
            ra0 = *(const float4*)&X[(m0 + ar0) * 1024 + ko + ac0];
            ra1 = *(const float4*)&X[(m0 + ar1) * 1024 + ko + ac1];
            rb0 = *(const float4*)&W[(ko + br0) * 1024 + n0 + bc0];
            rb1 = *(const float4*)&W[(ko + br1) * 1024 + n0 + bc1];
        }
        __syncthreads();
    }

    // ---- epilogue ----
#pragma unroll
    for (int am = 0; am < 2; am++) {
        int r0 = m0 + wm * 32 + am * 16 + g;
#pragma unroll
        for (int n = 0; n < 8; n++) {
            int c = n0 + wn * 64 + n * 8 + 2 * t4;
            *(float2*)&Y[(r0)     * 1024 + c] = make_float2(acc[am][n][0], acc[am][n][1]);
            *(float2*)&Y[(r0 + 8) * 1024 + c] = make_float2(acc[am][n][2], acc[am][n][3]);
        }
    }
}

// ---------------- Flash attention (tf32 MMA, causal + pad mask) ------------
// Block = (q-tile 128, head, batch). 128 threads = 4 warps; warp w owns query
// rows w*32..w*32+31 as two m16 sub-tiles (K/V fragments shared across both).
#define BRF 128
#define BCF 64
#define LDQ 68   // Qs/Ks/Ps stride (4g+t4 : conflict-free)
#define LDV 72   // Vs stride (8t4+g : conflict-free)

__global__ __launch_bounds__(128, 2)
void flash_tf32(const float* __restrict__ q, const float* __restrict__ k,
                const float* __restrict__ v, const int* __restrict__ kini,
                float* __restrict__ ctx) {
    extern __shared__ float smem[];
    float* Qs = smem;                   // 128 x 68
    float* Ks = Qs + BRF * LDQ;         // 64 x 68
    float* Ps = Ks + BCF * LDQ;         // 128 x 68
    float* Vs = Ps + BRF * LDQ;         // 64 x 72
    float* pmask = Vs + BCF * LDV;      // 64

    const int tid = threadIdx.x;
    const int lane = tid & 31;
    const int w = tid >> 5;
    const int g = lane >> 2, t4 = lane & 3;
    const int qt = blockIdx.x, h = blockIdx.y, b = blockIdx.z;
    const int q0 = qt * BRF;
    const int rowbase = b * S_;
    const int hoff = h * DH_;

    // Load Q tile 128x64 (scaled by 1/8, tf32-rounded, STS.128)
#pragma unroll
    for (int i = 0; i < 16; i++) {
        int idx = tid + i * 128;        // 0..2047 float4s
        int r = idx >> 4, c4 = (idx & 15) * 4;
        float4 t = *(const float4*)&q[(rowbase + q0 + r) * D_ + hoff + c4];
        *(float4*)&Qs[r * LDQ + c4] =
            make_float4(to_tf32(t.x * 0.125f), to_tf32(t.y * 0.125f),
                        to_tf32(t.z * 0.125f), to_tf32(t.w * 0.125f));
    }

    float m_[2][2], l_[2][2];
    float o[2][8][4];
#pragma unroll
    for (int am = 0; am < 2; am++) {
        m_[am][0] = -1e30f; m_[am][1] = -1e30f;
        l_[am][0] = 0.f;    l_[am][1] = 0.f;
#pragma unroll
        for (int n = 0; n < 8; n++)
#pragma unroll
            for (int e = 0; e < 4; e++) o[am][n][e] = 0.f;
    }

    const int qb = w * 32;
    const int ktmax = 2 * qt + 1;

    for (int kt = 0; kt <= ktmax; kt++) {
        const int k0 = kt * BCF;
        __syncthreads();   // Ks/Vs safe to overwrite (also orders Qs on kt=0)
#pragma unroll
        for (int i = 0; i < 8; i++) {
            int idx = tid + i * 128;    // 0..1023 float4s
            int r = idx >> 4, c4 = (idx & 15) * 4;
            float4 tk = *(const float4*)&k[(rowbase + k0 + r) * D_ + hoff + c4];
            *(float4*)&Ks[r * LDQ + c4] =
                make_float4(to_tf32(tk.x), to_tf32(tk.y), to_tf32(tk.z), to_tf32(tk.w));
            float4 tv = *(const float4*)&v[(rowbase + k0 + r) * D_ + hoff + c4];
            *(float4*)&Vs[r * LDV + c4] =
                make_float4(to_tf32(tv.x), to_tf32(tv.y), to_tf32(tv.z), to_tf32(tv.w));
        }
        if (tid < 64)
            pmask[tid] = (kini[rowbase + k0 + tid] != 0) ? 0.f : -1e10f;
        __syncthreads();

        // ---- S = Q @ K^T : 32 warp rows x 64 key cols --------------------
        float s[2][8][4];
#pragma unroll
        for (int am = 0; am < 2; am++)
#pragma unroll
            for (int n = 0; n < 8; n++)
#pragma unroll
                for (int e = 0; e < 4; e++) s[am][n][e] = 0.f;
#pragma unroll
        for (int ks = 0; ks < 8; ks++) {
            const int kk = ks * 8;
            uint32_t a[2][4];
#pragma unroll
            for (int am = 0; am < 2; am++) {
                int rq = qb + am * 16 + g;
                a[am][0] = __float_as_uint(Qs[(rq)     * LDQ + kk + t4]);
                a[am][1] = __float_as_uint(Qs[(rq + 8) * LDQ + kk + t4]);
                a[am][2] = __float_as_uint(Qs[(rq)     * LDQ + kk + t4 + 4]);
                a[am][3] = __float_as_uint(Qs[(rq + 8) * LDQ + kk + t4 + 4]);
            }
#pragma unroll
            for (int n = 0; n < 8; n++) {
                uint32_t b0 = __float_as_uint(Ks[(n * 8 + g) * LDQ + kk + t4]);
                uint32_t b1 = __float_as_uint(Ks[(n * 8 + g) * LDQ + kk + t4 + 4]);
                mma_tf32(s[0][n], a[0], b0, b1);
                mma_tf32(s[1][n], a[1], b0, b1);
            }
        }

        // ---- masks + online softmax per am block -------------------------
#pragma unroll
        for (int am = 0; am < 2; am++) {
            const int gq0 = q0 + qb + am * 16 + g;
            const int gq1 = gq0 + 8;
#pragma unroll
            for (int n = 0; n < 8; n++) {
                int c0 = n * 8 + 2 * t4;
#pragma unroll
                for (int e = 0; e < 2; e++) {
                    int gk = k0 + c0 + e;
                    float pm = pmask[c0 + e];
                    s[am][n][e]     += (gk > gq0) ? -1e10f : pm;
                    s[am][n][e + 2] += (gk > gq1) ? -1e10f : pm;
                }
            }
            float rm0 = -1e30f, rm1 = -1e30f;
#pragma unroll
            for (int n = 0; n < 8; n++) {
                rm0 = fmaxf(rm0, fmaxf(s[am][n][0], s[am][n][1]));
                rm1 = fmaxf(rm1, fmaxf(s[am][n][2], s[am][n][3]));
            }
#pragma unroll
            for (int msk = 1; msk < 4; msk <<= 1) {
                rm0 = fmaxf(rm0, __shfl_xor_sync(0xffffffffu, rm0, msk));
                rm1 = fmaxf(rm1, __shfl_xor_sync(0xffffffffu, rm1, msk));
            }
            float mn0 = fmaxf(m_[am][0], rm0), mn1 = fmaxf(m_[am][1], rm1);
            float rs0 = 0.f, rs1 = 0.f;
#pragma unroll
            for (int n = 0; n < 8; n++) {
                s[am][n][0] = __expf(s[am][n][0] - mn0);
                s[am][n][1] = __expf(s[am][n][1] - mn0);
                s[am][n][2] = __expf(s[am][n][2] - mn1);
                s[am][n][3] = __expf(s[am][n][3] - mn1);
                rs0 += s[am][n][0] + s[am][n][1];
                rs1 += s[am][n][2] + s[am][n][3];
            }
#pragma unroll
            for (int msk = 1; msk < 4; msk <<= 1) {
                rs0 += __shfl_xor_sync(0xffffffffu, rs0, msk);
                rs1 += __shfl_xor_sync(0xffffffffu, rs1, msk);
            }
            float c0s = __expf(m_[am][0] - mn0), c1s = __expf(m_[am][1] - mn1);
            l_[am][0] = l_[am][0] * c0s + rs0; m_[am][0] = mn0;
            l_[am][1] = l_[am][1] * c1s + rs1; m_[am][1] = mn1;
#pragma unroll
            for (int n = 0; n < 8; n++) {
                o[am][n][0] *= c0s; o[am][n][1] *= c0s;
                o[am][n][2] *= c1s; o[am][n][3] *= c1s;
            }

            // stage P (tf32, float2 stores; rows owned exclusively by warp)
            const int rq = qb + am * 16 + g;
#pragma unroll
            for (int n = 0; n < 8; n++) {
                int c = n * 8 + 2 * t4;
                *(float2*)&Ps[(rq)     * LDQ + c] =
                    make_float2(to_tf32(s[am][n][0]), to_tf32(s[am][n][1]));
                *(float2*)&Ps[(rq + 8) * LDQ + c] =
                    make_float2(to_tf32(s[am][n][2]), to_tf32(s[am][n][3]));
            }
        }
        __syncwarp();

        // ---- O += P @ V (V fragments shared across both am blocks) -------
#pragma unroll
        for (int ks = 0; ks < 8; ks++) {
            const int kk = ks * 8;
            uint32_t a[2][4];
#pragma unroll
            for (int am = 0; am < 2; am++) {
                int rq = qb + am * 16 + g;
                a[am][0] = __float_as_uint(Ps[(rq)     * LDQ + kk + t4]);
                a[am][1] = __float_as_uint(Ps[(rq + 8) * LDQ + kk + t4]);
                a[am][2] = __float_as_uint(Ps[(rq)     * LDQ + kk + t4 + 4]);
                a[am][3] = __float_as_uint(Ps[(rq + 8) * LDQ + kk + t4 + 4]);
            }
#pragma unroll
            for (int n = 0; n < 8; n++) {
                uint32_t b0 = __float_as_uint(Vs[(kk + t4)     * LDV + n * 8 + g]);
                uint32_t b1 = __float_as_uint(Vs[(kk + t4 + 4) * LDV + n * 8 + g]);
                mma_tf32(o[0][n], a[0], b0, b1);
                mma_tf32(o[1][n], a[1], b0, b1);
            }
        }
        __syncwarp();  // Ps reads done before next iteration overwrites
    }

    // epilogue: normalize, store ctx[M, D] (head slice at hoff)
#pragma unroll
    for (int am = 0; am < 2; am++) {
        float inv0 = 1.f / l_[am][0], inv1 = 1.f / l_[am][1];
        const int r0 = rowbase + q0 + qb + am * 16 + g;
#pragma unroll
        for (int n = 0; n < 8; n++) {
            int c = hoff + n * 8 + 2 * t4;
            *(float2*)&ctx[(r0)     * D_ + c] =
                make_float2(o[am][n][0] * inv0, o[am][n][1] * inv0);
            *(float2*)&ctx[(r0 + 8) * D_ + c] =
                make_float2(o[am][n][2] * inv1, o[am][n][3] * inv1);
        }
    }
}

// ---------------- launch -----------------------------------------------------
extern "C" void kernel_launch(void* const* d_in, const int* in_sizes, int n_in,
                              void* d_out, int out_size) {
    const float* Q_emb = (const float*)d_in[0];
    const float* K_emb = (const float*)d_in[1];
    const float* V_emb = (const float*)d_in[2];
    // d_in[3] = Q_ini (unused by reference math)
    const int*   K_ini = (const int*)d_in[4];
    const float* WQ = (const float*)d_in[5];
    const float* WK = (const float*)d_in[6];
    const float* WV = (const float*)d_in[7];
    const float* WO = (const float*)d_in[8];
    float* out = (float*)d_out;

    float *gq, *gk, *gv, *gctx;
    cudaGetSymbolAddress((void**)&gq,   g_q);
    cudaGetSymbolAddress((void**)&gk,   g_k);
    cudaGetSymbolAddress((void**)&gv,   g_v);
    cudaGetSymbolAddress((void**)&gctx, g_ctx);

    const int smem_flash =
        (BRF * LDQ + BCF * LDQ + BRF * LDQ + BCF * LDV + 64) * (int)sizeof(float);
    cudaFuncSetAttribute(flash_tf32, cudaFuncAttributeMaxDynamicSharedMemorySize,
                         smem_flash);

    // fused QKV projections: grid.z = 3
    dim3 ggrid3(8, 64, 3);
    gemm_tf32<<<ggrid3, 256>>>(Q_emb, K_emb, V_emb, WQ, WK, WV, gq, gk, gv);

    dim3 fgrid(S_ / BRF, H_, B_);  // (16, 16, 4)
    flash_tf32<<<fgrid, 128, smem_flash>>>(gq, gk, gv, K_ini, gctx);

    // output projection: grid.z = 1
    dim3 ggrid1(8, 64, 1);
    gemm_tf32<<<ggrid1, 256>>>(gctx, gctx, gctx, WO, WO, WO, out, out, out);
}

// round 10
// speedup vs baseline: 6.0383x; 1.4581x over previous
#include <cuda_runtime.h>
#include <cuda_fp16.h>
#include <cstdint>

// Problem constants
#define B_   4
#define S_   2048
#define H_   16
#define DH_  64
#define D_   1024
#define M_   (B_*S_)   // 8192 rows

// ---------------- scratch (device globals: no allocation allowed) ----------
__device__ float g_q[M_ * D_];
__device__ float g_k[M_ * D_];
__device__ float g_v[M_ * D_];
__device__ float g_ctx[M_ * D_];

// ---------------- fp16 helpers ---------------------------------------------
__device__ __forceinline__ uint32_t ph2(float a, float b) {
    __half2 h = __floats2half2_rn(a, b);   // .x = a (low), .y = b (high)
    return *reinterpret_cast<uint32_t*>(&h);
}

// mma.sync m16n8k16 fp16 in / fp32 accum
__device__ __forceinline__ void mma_f16(float c[4], const uint32_t a[4],
                                        uint32_t b0, uint32_t b1) {
    asm volatile(
        "mma.sync.aligned.m16n8k16.row.col.f32.f16.f16.f32 "
        "{%0,%1,%2,%3}, {%4,%5,%6,%7}, {%8,%9}, {%0,%1,%2,%3};\n"
        : "+f"(c[0]), "+f"(c[1]), "+f"(c[2]), "+f"(c[3])
        : "r"(a[0]), "r"(a[1]), "r"(a[2]), "r"(a[3]), "r"(b0), "r"(b1));
}

// ---------------- fp16 GEMM: Y[M,1024] = X[M,1024] @ W[1024,1024] ----------
// 128x128 tile, K-chunk 16 (one k16 MMA step), DOUBLE-BUFFERED smem,
// 256 threads (8 warps 4x2), warp = 32x64. fp16 operands, fp32 accum.
// Smem units are uint32 (= half2 k-pairs).
#define LDA2 12          // As pair-stride: banks 4g+t4 conflict-free (12%8==4)
#define LDB2 136         // Bs pair-row stride: banks 8t4+g conflict-free
#define ASZ2 (128 * LDA2)  // 1536
#define BSZ2 (8 * LDB2)    // 1088
#define NCH 64             // 1024/16

__global__ __launch_bounds__(256, 2)
void gemm_f16(const float* __restrict__ X0, const float* __restrict__ X1,
              const float* __restrict__ X2,
              const float* __restrict__ W0, const float* __restrict__ W1,
              const float* __restrict__ W2,
              float* __restrict__ Y0, float* __restrict__ Y1,
              float* __restrict__ Y2) {
    __shared__ uint32_t As2[2 * ASZ2];
    __shared__ uint32_t Bs2[2 * BSZ2];

    const int z = blockIdx.z;
    const float* X = (z == 0) ? X0 : (z == 1) ? X1 : X2;
    const float* W = (z == 0) ? W0 : (z == 1) ? W1 : W2;
    float*       Y = (z == 0) ? Y0 : (z == 1) ? Y1 : Y2;

    const int tid = threadIdx.x;
    const int lane = tid & 31;
    const int wid = tid >> 5;
    const int g = lane >> 2, t4 = lane & 3;
    const int wm = wid & 3, wn = wid >> 2;
    const int m0 = blockIdx.y * 128, n0 = blockIdx.x * 128;

    // fill coords: A two float4 per thread (rows 0..127, 16 fp32 per row)
    const int ar0 = tid >> 2,          ac0 = (tid & 3) * 4;
    const int ar1 = (tid + 256) >> 2,  ac1 = ((tid + 256) & 3) * 4;
    // B: one unit per thread: k-pair row bkp, 4 cols at bn4 (pack 2 W rows)
    const int bkp = tid >> 5, bn4 = (tid & 31) * 4;

    float acc[2][8][4];
#pragma unroll
    for (int am = 0; am < 2; am++)
#pragma unroll
        for (int n = 0; n < 8; n++)
#pragma unroll
            for (int e = 0; e < 4; e++) acc[am][n][e] = 0.f;

    float4 ra0, ra1, rba, rbb;

    // ---- prologue: LDG chunk0 -> STS buf0 -> LDG chunk1 -> sync ----
    ra0 = *(const float4*)&X[(m0 + ar0) * 1024 + ac0];
    ra1 = *(const float4*)&X[(m0 + ar1) * 1024 + ac1];
    rba = *(const float4*)&W[(2 * bkp)     * 1024 + n0 + bn4];
    rbb = *(const float4*)&W[(2 * bkp + 1) * 1024 + n0 + bn4];

    *(uint2*)&As2[ar0 * LDA2 + ac0 / 2] =
        make_uint2(ph2(ra0.x, ra0.y), ph2(ra0.z, ra0.w));
    *(uint2*)&As2[ar1 * LDA2 + ac1 / 2] =
        make_uint2(ph2(ra1.x, ra1.y), ph2(ra1.z, ra1.w));
    *(uint4*)&Bs2[bkp * LDB2 + bn4] =
        make_uint4(ph2(rba.x, rbb.x), ph2(rba.y, rbb.y),
                   ph2(rba.z, rbb.z), ph2(rba.w, rbb.w));

    ra0 = *(const float4*)&X[(m0 + ar0) * 1024 + 16 + ac0];
    ra1 = *(const float4*)&X[(m0 + ar1) * 1024 + 16 + ac1];
    rba = *(const float4*)&W[(16 + 2 * bkp)     * 1024 + n0 + bn4];
    rbb = *(const float4*)&W[(16 + 2 * bkp + 1) * 1024 + n0 + bn4];
    __syncthreads();

    for (int kc = 0; kc < NCH; kc++) {
        const uint32_t* Ab = As2 + (kc & 1) * ASZ2;
        const uint32_t* Bb = Bs2 + (kc & 1) * BSZ2;

        // ---- compute chunk kc: one k16 step, 16 MMAs/warp ----
        uint32_t a[2][4];
#pragma unroll
        for (int am = 0; am < 2; am++) {
            int rm = wm * 32 + am * 16;
            a[am][0] = Ab[(rm + g)     * LDA2 + t4];
            a[am][1] = Ab[(rm + g + 8) * LDA2 + t4];
            a[am][2] = Ab[(rm + g)     * LDA2 + t4 + 4];
            a[am][3] = Ab[(rm + g + 8) * LDA2 + t4 + 4];
        }
        const int cn = wn * 64;
#pragma unroll
        for (int n = 0; n < 8; n++) {
            uint32_t b0 = Bb[(t4)     * LDB2 + cn + n * 8 + g];
            uint32_t b1 = Bb[(t4 + 4) * LDB2 + cn + n * 8 + g];
            mma_f16(acc[0][n], a[0], b0, b1);
            mma_f16(acc[1][n], a[1], b0, b1);
        }

        // ---- STS chunk kc+1 into other buffer ----
        if (kc + 1 < NCH) {
            uint32_t* An = As2 + ((kc + 1) & 1) * ASZ2;
            uint32_t* Bn = Bs2 + ((kc + 1) & 1) * BSZ2;
            *(uint2*)&An[ar0 * LDA2 + ac0 / 2] =
                make_uint2(ph2(ra0.x, ra0.y), ph2(ra0.z, ra0.w));
            *(uint2*)&An[ar1 * LDA2 + ac1 / 2] =
                make_uint2(ph2(ra1.x, ra1.y), ph2(ra1.z, ra1.w));
            *(uint4*)&Bn[bkp * LDB2 + bn4] =
                make_uint4(ph2(rba.x, rbb.x), ph2(rba.y, rbb.y),
                           ph2(rba.z, rbb.z), ph2(rba.w, rbb.w));
        }
        // ---- LDG chunk kc+2 ----
        if (kc + 2 < NCH) {
            const int ko = (kc + 2) * 16;
            ra0 = *(const float4*)&X[(m0 + ar0) * 1024 + ko + ac0];
            ra1 = *(const float4*)&X[(m0 + ar1) * 1024 + ko + ac1];
            rba = *(const float4*)&W[(ko + 2 * bkp)     * 1024 + n0 + bn4];
            rbb = *(const float4*)&W[(ko + 2 * bkp + 1) * 1024 + n0 + bn4];
        }
        __syncthreads();
    }

    // ---- epilogue (fp32 accum stores) ----
#pragma unroll
    for (int am = 0; am < 2; am++) {
        int r0 = m0 + wm * 32 + am * 16 + g;
#pragma unroll
        for (int n = 0; n < 8; n++) {
            int c = n0 + wn * 64 + n * 8 + 2 * t4;
            *(float2*)&Y[(r0)     * 1024 + c] = make_float2(acc[am][n][0], acc[am][n][1]);
            *(float2*)&Y[(r0 + 8) * 1024 + c] = make_float2(acc[am][n][2], acc[am][n][3]);
        }
    }
}

// ---------------- Flash attention (fp16 MMA, causal + pad mask) ------------
// Block = (q-tile 128, head, batch). 128 threads = 4 warps; warp w owns query
// rows w*32..w*32+31 as two m16 sub-tiles. All operands fp16 in smem (half2
// packed in uint32 units), softmax + accumulators fp32.
#define BRF 128
#define BCF 64
#define LDQ2 36   // Qs/Ks/Ps pair-stride (4g+t4 conflict-free: 36%8==4)
#define LDV2 72   // Vs pair-row stride  (8t4+g conflict-free: 72%32==8)
// smem (uint32 units): Qs 128*36, Ks 64*36, Ps 128*36, Vs 32*72, pmask 64 f32
#define FQ_OFF 0
#define FK_OFF (128 * LDQ2)                 // 4608
#define FP_OFF (FK_OFF + 64 * LDQ2)        // 6912
#define FV_OFF (FP_OFF + 128 * LDQ2)       // 11520
#define FM_OFF (FV_OFF + 32 * LDV2)        // 13824
#define FSMEM_U32 (FM_OFF + 64)            // 13888 -> 55552 bytes

__global__ __launch_bounds__(128, 3)
void flash_f16(const float* __restrict__ q, const float* __restrict__ k,
               const float* __restrict__ v, const int* __restrict__ kini,
               float* __restrict__ ctx) {
    extern __shared__ uint32_t smu[];
    uint32_t* Qs = smu + FQ_OFF;
    uint32_t* Ks = smu + FK_OFF;
    uint32_t* Ps = smu + FP_OFF;
    uint32_t* Vs = smu + FV_OFF;
    float* pmask = (float*)(smu + FM_OFF);

    const int tid = threadIdx.x;
    const int lane = tid & 31;
    const int w = tid >> 5;
    const int g = lane >> 2, t4 = lane & 3;
    const int qt = (int)gridDim.x - 1 - (int)blockIdx.x;  // heavy tiles first
    const int h = blockIdx.y, b = blockIdx.z;
    const int q0 = qt * BRF;
    const int rowbase = b * S_;
    const int hoff = h * DH_;

    // Load Q tile 128x64 (scaled by 1/8, fp16-packed)
#pragma unroll
    for (int i = 0; i < 16; i++) {
        int idx = tid + i * 128;        // 0..2047 float4 units
        int r = idx >> 4, c4 = (idx & 15) * 4;
        float4 t = *(const float4*)&q[(rowbase + q0 + r) * D_ + hoff + c4];
        *(uint2*)&Qs[r * LDQ2 + c4 / 2] =
            make_uint2(ph2(t.x * 0.125f, t.y * 0.125f),
                       ph2(t.z * 0.125f, t.w * 0.125f));
    }

    float m_[2][2], l_[2][2];
    float o[2][8][4];
#pragma unroll
    for (int am = 0; am < 2; am++) {
        m_[am][0] = -1e30f; m_[am][1] = -1e30f;
        l_[am][0] = 0.f;    l_[am][1] = 0.f;
#pragma unroll
        for (int n = 0; n < 8; n++)
#pragma unroll
            for (int e = 0; e < 4; e++) o[am][n][e] = 0.f;
    }

    const int qb = w * 32;
    const int ktmax = 2 * qt + 1;

    for (int kt = 0; kt <= ktmax; kt++) {
        const int k0 = kt * BCF;
        __syncthreads();   // Ks/Vs/Ps safe to overwrite (orders Qs on kt=0)
        // K tile 64x64 -> Ks[row][pair]
#pragma unroll
        for (int i = 0; i < 8; i++) {
            int idx = tid + i * 128;    // 0..1023 float4 units
            int r = idx >> 4, c4 = (idx & 15) * 4;
            float4 tk = *(const float4*)&k[(rowbase + k0 + r) * D_ + hoff + c4];
            *(uint2*)&Ks[r * LDQ2 + c4 / 2] =
                make_uint2(ph2(tk.x, tk.y), ph2(tk.z, tk.w));
        }
        // V tile 64x64 -> Vs[keypair][col] (pack adjacent key rows)
#pragma unroll
        for (int i = 0; i < 4; i++) {
            int u = tid + i * 128;      // 0..511 units: 32 kp x 16 col4
            int kp = u >> 4, c4 = (u & 15) * 4;
            float4 va = *(const float4*)&v[(rowbase + k0 + 2 * kp)     * D_ + hoff + c4];
            float4 vb = *(const float4*)&v[(rowbase + k0 + 2 * kp + 1) * D_ + hoff + c4];
            *(uint4*)&Vs[kp * LDV2 + c4] =
                make_uint4(ph2(va.x, vb.x), ph2(va.y, vb.y),
                           ph2(va.z, vb.z), ph2(va.w, vb.w));
        }
        if (tid < 64)
            pmask[tid] = (kini[rowbase + k0 + tid] != 0) ? 0.f : -1e10f;
        __syncthreads();

        // ---- S = Q @ K^T : 32 warp rows x 64 key cols (k16 x 4 steps) ----
        float s[2][8][4];
#pragma unroll
        for (int am = 0; am < 2; am++)
#pragma unroll
            for (int n = 0; n < 8; n++)
#pragma unroll
                for (int e = 0; e < 4; e++) s[am][n][e] = 0.f;
#pragma unroll
        for (int ks = 0; ks < 4; ks++) {
            const int kb = ks * 8;
            uint32_t a[2][4];
#pragma unroll
            for (int am = 0; am < 2; am++) {
                int rq = qb + am * 16;
                a[am][0] = Qs[(rq + g)     * LDQ2 + kb + t4];
                a[am][1] = Qs[(rq + g + 8) * LDQ2 + kb + t4];
                a[am][2] = Qs[(rq + g)     * LDQ2 + kb + t4 + 4];
                a[am][3] = Qs[(rq + g + 8) * LDQ2 + kb + t4 + 4];
            }
#pragma unroll
            for (int n = 0; n < 8; n++) {
                uint32_t b0 = Ks[(n * 8 + g) * LDQ2 + kb + t4];
                uint32_t b1 = Ks[(n * 8 + g) * LDQ2 + kb + t4 + 4];
                mma_f16(s[0][n], a[0], b0, b1);
                mma_f16(s[1][n], a[1], b0, b1);
            }
        }

        // ---- masks + online softmax per am block -------------------------
#pragma unroll
        for (int am = 0; am < 2; am++) {
            const int gq0 = q0 + qb + am * 16 + g;
            const int gq1 = gq0 + 8;
#pragma unroll
            for (int n = 0; n < 8; n++) {
                int c0 = n * 8 + 2 * t4;
#pragma unroll
                for (int e = 0; e < 2; e++) {
                    int gk = k0 + c0 + e;
                    float pm = pmask[c0 + e];
                    s[am][n][e]     += (gk > gq0) ? -1e10f : pm;
                    s[am][n][e + 2] += (gk > gq1) ? -1e10f : pm;
                }
            }
            float rm0 = -1e30f, rm1 = -1e30f;
#pragma unroll
            for (int n = 0; n < 8; n++) {
                rm0 = fmaxf(rm0, fmaxf(s[am][n][0], s[am][n][1]));
                rm1 = fmaxf(rm1, fmaxf(s[am][n][2], s[am][n][3]));
            }
#pragma unroll
            for (int msk = 1; msk < 4; msk <<= 1) {
                rm0 = fmaxf(rm0, __shfl_xor_sync(0xffffffffu, rm0, msk));
                rm1 = fmaxf(rm1, __shfl_xor_sync(0xffffffffu, rm1, msk));
            }
            float mn0 = fmaxf(m_[am][0], rm0), mn1 = fmaxf(m_[am][1], rm1);
            float rs0 = 0.f, rs1 = 0.f;
#pragma unroll
            for (int n = 0; n < 8; n++) {
                s[am][n][0] = __expf(s[am][n][0] - mn0);
                s[am][n][1] = __expf(s[am][n][1] - mn0);
                s[am][n][2] = __expf(s[am][n][2] - mn1);
                s[am][n][3] = __expf(s[am][n][3] - mn1);
                rs0 += s[am][n][0] + s[am][n][1];
                rs1 += s[am][n][2] + s[am][n][3];
            }
#pragma unroll
            for (int msk = 1; msk < 4; msk <<= 1) {
                rs0 += __shfl_xor_sync(0xffffffffu, rs0, msk);
                rs1 += __shfl_xor_sync(0xffffffffu, rs1, msk);
            }
            float c0s = __expf(m_[am][0] - mn0), c1s = __expf(m_[am][1] - mn1);
            l_[am][0] = l_[am][0] * c0s + rs0; m_[am][0] = mn0;
            l_[am][1] = l_[am][1] * c1s + rs1; m_[am][1] = mn1;
#pragma unroll
            for (int n = 0; n < 8; n++) {
                o[am][n][0] *= c0s; o[am][n][1] *= c0s;
                o[am][n][2] *= c1s; o[am][n][3] *= c1s;
            }

            // stage P as fp16 pairs (cols 2t4,2t4+1 pack into one half2)
            const int rq = qb + am * 16;
#pragma unroll
            for (int n = 0; n < 8; n++) {
                Ps[(rq + g)     * LDQ2 + n * 4 + t4] = ph2(s[am][n][0], s[am][n][1]);
                Ps[(rq + g + 8) * LDQ2 + n * 4 + t4] = ph2(s[am][n][2], s[am][n][3]);
            }
        }
        __syncwarp();

        // ---- O += P @ V (k16 x 4 steps over 64 keys) ---------------------
#pragma unroll
        for (int ks = 0; ks < 4; ks++) {
            const int kb = ks * 8;
            uint32_t a[2][4];
#pragma unroll
            for (int am = 0; am < 2; am++) {
                int rq = qb + am * 16;
                a[am][0] = Ps[(rq + g)     * LDQ2 + kb + t4];
                a[am][1] = Ps[(rq + g + 8) * LDQ2 + kb + t4];
                a[am][2] = Ps[(rq + g)     * LDQ2 + kb + t4 + 4];
                a[am][3] = Ps[(rq + g + 8) * LDQ2 + kb + t4 + 4];
            }
#pragma unroll
            for (int n = 0; n < 8; n++) {
                uint32_t b0 = Vs[(kb + t4)     * LDV2 + n * 8 + g];
                uint32_t b1 = Vs[(kb + t4 + 4) * LDV2 + n * 8 + g];
                mma_f16(o[0][n], a[0], b0, b1);
                mma_f16(o[1][n], a[1], b0, b1);
            }
        }
        __syncwarp();  // Ps reads done before next iteration overwrites
    }

    // epilogue: normalize, store ctx[M, D] (head slice at hoff)
#pragma unroll
    for (int am = 0; am < 2; am++) {
        float inv0 = 1.f / l_[am][0], inv1 = 1.f / l_[am][1];
        const int r0 = rowbase + q0 + qb + am * 16 + g;
#pragma unroll
        for (int n = 0; n < 8; n++) {
            int c = hoff + n * 8 + 2 * t4;
            *(float2*)&ctx[(r0)     * D_ + c] =
                make_float2(o[am][n][0] * inv0, o[am][n][1] * inv0);
            *(float2*)&ctx[(r0 + 8) * D_ + c] =
                make_float2(o[am][n][2] * inv1, o[am][n][3] * inv1);
        }
    }
}

// ---------------- launch -----------------------------------------------------
extern "C" void kernel_launch(void* const* d_in, const int* in_sizes, int n_in,
                              void* d_out, int out_size) {
    const float* Q_emb = (const float*)d_in[0];
    const float* K_emb = (const float*)d_in[1];
    const float* V_emb = (const float*)d_in[2];
    // d_in[3] = Q_ini (unused by reference math)
    const int*   K_ini = (const int*)d_in[4];
    const float* WQ = (const float*)d_in[5];
    const float* WK = (const float*)d_in[6];
    const float* WV = (const float*)d_in[7];
    const float* WO = (const float*)d_in[8];
    float* out = (float*)d_out;

    float *gq, *gk, *gv, *gctx;
    cudaGetSymbolAddress((void**)&gq,   g_q);
    cudaGetSymbolAddress((void**)&gk,   g_k);
    cudaGetSymbolAddress((void**)&gv,   g_v);
    cudaGetSymbolAddress((void**)&gctx, g_ctx);

    const int smem_flash = FSMEM_U32 * (int)sizeof(uint32_t);  // ~55.6 KB
    cudaFuncSetAttribute(flash_f16, cudaFuncAttributeMaxDynamicSharedMemorySize,
                         smem_flash);

    // fused QKV projections: grid.z = 3
    dim3 ggrid3(8, 64, 3);
    gemm_f16<<<ggrid3, 256>>>(Q_emb, K_emb, V_emb, WQ, WK, WV, gq, gk, gv);

    dim3 fgrid(S_ / BRF, H_, B_);  // (16, 16, 4)
    flash_f16<<<fgrid, 128, smem_flash>>>(gq, gk, gv, K_ini, gctx);

    // output projection: grid.z = 1
    dim3 ggrid1(8, 64, 1);
    gemm_f16<<<ggrid1, 256>>>(gctx, gctx, gctx, WO, WO, WO, out, out, out);
}

// round 11
// speedup vs baseline: 6.8746x; 1.1385x over previous
#include <cuda_runtime.h>
#include <cuda_fp16.h>
#include <cstdint>

// Problem constants
#define B_   4
#define S_   2048
#define H_   16
#define DH_  64
#define D_   1024
#define M_   (B_*S_)   // 8192 rows
#define DU   512       // row stride in uint32 (half2) units

// ---------------- scratch (device globals: no allocation allowed) ----------
// fp16 storage everywhere (uint32 = half2 k-pairs)
__device__ uint32_t g_q[M_ * DU];
__device__ uint32_t g_k[M_ * DU];
__device__ uint32_t g_v[M_ * DU];
__device__ uint32_t g_ctx[M_ * DU];
__device__ uint32_t g_xh[3 * M_ * DU];       // fp16 embeddings Q,K,V
__device__ uint32_t g_wp[4 * 512 * 1024];    // packed weights [kp][n]

// ---------------- fp16 helpers ---------------------------------------------
__device__ __forceinline__ uint32_t ph2(float a, float b) {
    __half2 h = __floats2half2_rn(a, b);   // .x = a (low), .y = b (high)
    return *reinterpret_cast<uint32_t*>(&h);
}

// mma.sync m16n8k16 fp16 in / fp32 accum
__device__ __forceinline__ void mma_f16(float c[4], const uint32_t a[4],
                                        uint32_t b0, uint32_t b1) {
    asm volatile(
        "mma.sync.aligned.m16n8k16.row.col.f32.f16.f16.f32 "
        "{%0,%1,%2,%3}, {%4,%5,%6,%7}, {%8,%9}, {%0,%1,%2,%3};\n"
        : "+f"(c[0]), "+f"(c[1]), "+f"(c[2]), "+f"(c[3])
        : "r"(a[0]), "r"(a[1]), "r"(a[2]), "r"(a[3]), "r"(b0), "r"(b1));
}

// ---------------- pre-pass: fp32 embeddings -> fp16 -------------------------
__global__ void conv_h(const float* __restrict__ Q, const float* __restrict__ K,
                       const float* __restrict__ V, uint32_t* __restrict__ out) {
    const float* src = (blockIdx.z == 0) ? Q : (blockIdx.z == 1) ? K : V;
    uint32_t* dst = out + (size_t)blockIdx.z * (M_ * DU);
    int id = (blockIdx.x * 256 + threadIdx.x) * 4;   // u32 index
    float4 a = *(const float4*)&src[2 * id];
    float4 b = *(const float4*)&src[2 * id + 4];
    *(uint4*)&dst[id] = make_uint4(ph2(a.x, a.y), ph2(a.z, a.w),
                                   ph2(b.x, b.y), ph2(b.z, b.w));
}

// ---------------- pre-pass: pack W into B k-pair layout ---------------------
// Wp[kp][n] = half2(W[2kp][n], W[2kp+1][n])
__global__ void pack_w(const float* __restrict__ Wq, const float* __restrict__ Wk,
                       const float* __restrict__ Wv, const float* __restrict__ Wo,
                       uint32_t* __restrict__ out) {
    const int z = blockIdx.z;
    const float* W = (z == 0) ? Wq : (z == 1) ? Wk : (z == 2) ? Wv : Wo;
    uint32_t* dst = out + (size_t)z * (512 * 1024);
    const int kp = blockIdx.x;            // 0..511
    const int n4 = threadIdx.x * 4;       // 0..1020
    float4 a = *(const float4*)&W[(2 * kp)     * 1024 + n4];
    float4 b = *(const float4*)&W[(2 * kp + 1) * 1024 + n4];
    *(uint4*)&dst[kp * 1024 + n4] =
        make_uint4(ph2(a.x, b.x), ph2(a.y, b.y), ph2(a.z, b.z), ph2(a.w, b.w));
}

// ---------------- fp16 GEMM: Y[M,1024] = X[M,1024] @ W ----------------------
// All-fp16 operands in memory. 128x128 tile, K-chunk 32 (2 k16 steps),
// double-buffered smem, 256 threads (8 warps 4x2), warp = 32x64.
// mode 0: fp16 out (z-indexed; z==0 output scaled 0.125 = Q pre-scale)
// mode 1: fp32 out to Yf.
#define LDA2 20          // As pair-stride: banks 4g+t4 conflict-free (20%8==4)
#define LDB2 136         // Bs pair-row stride: banks 8t4+g conflict-free
#define ASZ2 (128 * LDA2)  // 2560
#define BSZ2 (16 * LDB2)   // 2176
#define NCH 32             // 1024/32

__global__ __launch_bounds__(256, 2)
void gemm_f16(const uint32_t* __restrict__ Xb, const uint32_t* __restrict__ Wpb,
              uint32_t* __restrict__ Yh0, uint32_t* __restrict__ Yh1,
              uint32_t* __restrict__ Yh2, float* __restrict__ Yf, int mode) {
    __shared__ uint32_t As2[2 * ASZ2];
    __shared__ uint32_t Bs2[2 * BSZ2];

    const int z = blockIdx.z;
    const uint32_t* X = Xb + (size_t)z * (M_ * DU);
    const uint32_t* W = Wpb + (size_t)z * (512 * 1024);

    const int tid = threadIdx.x;
    const int lane = tid & 31;
    const int wid = tid >> 5;
    const int g = lane >> 2, t4 = lane & 3;
    const int wm = wid & 3, wn = wid >> 2;
    const int m0 = blockIdx.y * 128, n0 = blockIdx.x * 128;

    float acc[2][8][4];
#pragma unroll
    for (int am = 0; am < 2; am++)
#pragma unroll
        for (int n = 0; n < 8; n++)
#pragma unroll
            for (int e = 0; e < 4; e++) acc[am][n][e] = 0.f;

    uint4 ra[2], rb[2];

    // ---- prologue: LDG chunk0 -> STS buf0 -> LDG chunk1 -> sync ----
#pragma unroll
    for (int j = 0; j < 2; j++) {
        int id = tid + j * 256;
        int r = id >> 2, q4 = (id & 3) * 4;
        ra[j] = *(const uint4*)&X[(m0 + r) * DU + q4];
        int kp = id >> 5, n4 = (id & 31) * 4;
        rb[j] = *(const uint4*)&W[kp * 1024 + n0 + n4];
    }
#pragma unroll
    for (int j = 0; j < 2; j++) {
        int id = tid + j * 256;
        int r = id >> 2, q4 = (id & 3) * 4;
        *(uint4*)&As2[r * LDA2 + q4] = ra[j];
        int kp = id >> 5, n4 = (id & 31) * 4;
        *(uint4*)&Bs2[kp * LDB2 + n4] = rb[j];
    }
#pragma unroll
    for (int j = 0; j < 2; j++) {
        int id = tid + j * 256;
        int r = id >> 2, q4 = (id & 3) * 4;
        ra[j] = *(const uint4*)&X[(m0 + r) * DU + 16 + q4];
        int kp = id >> 5, n4 = (id & 31) * 4;
        rb[j] = *(const uint4*)&W[(16 + kp) * 1024 + n0 + n4];
    }
    __syncthreads();

    for (int kc = 0; kc < NCH; kc++) {
        const uint32_t* Ab = As2 + (kc & 1) * ASZ2;
        const uint32_t* Bb = Bs2 + (kc & 1) * BSZ2;

        // ---- compute chunk kc: 2 k16 steps, 32 MMAs/warp ----
#pragma unroll
        for (int ks = 0; ks < 2; ks++) {
            const int kb = ks * 8;
            uint32_t a[2][4];
#pragma unroll
            for (int am = 0; am < 2; am++) {
                int rm = wm * 32 + am * 16;
                a[am][0] = Ab[(rm + g)     * LDA2 + kb + t4];
                a[am][1] = Ab[(rm + g + 8) * LDA2 + kb + t4];
                a[am][2] = Ab[(rm + g)     * LDA2 + kb + t4 + 4];
                a[am][3] = Ab[(rm + g + 8) * LDA2 + kb + t4 + 4];
            }
            const int cn = wn * 64;
#pragma unroll
            for (int n = 0; n < 8; n++) {
                uint32_t b0 = Bb[(kb + t4)     * LDB2 + cn + n * 8 + g];
                uint32_t b1 = Bb[(kb + t4 + 4) * LDB2 + cn + n * 8 + g];
                mma_f16(acc[0][n], a[0], b0, b1);
                mma_f16(acc[1][n], a[1], b0, b1);
            }
        }

        // ---- STS chunk kc+1 into other buffer ----
        if (kc + 1 < NCH) {
            uint32_t* An = As2 + ((kc + 1) & 1) * ASZ2;
            uint32_t* Bn = Bs2 + ((kc + 1) & 1) * BSZ2;
#pragma unroll
            for (int j = 0; j < 2; j++) {
                int id = tid + j * 256;
                int r = id >> 2, q4 = (id & 3) * 4;
                *(uint4*)&An[r * LDA2 + q4] = ra[j];
                int kp = id >> 5, n4 = (id & 31) * 4;
                *(uint4*)&Bn[kp * LDB2 + n4] = rb[j];
            }
        }
        // ---- LDG chunk kc+2 ----
        if (kc + 2 < NCH) {
            const int ku = (kc + 2) * 16;
#pragma unroll
            for (int j = 0; j < 2; j++) {
                int id = tid + j * 256;
                int r = id >> 2, q4 = (id & 3) * 4;
                ra[j] = *(const uint4*)&X[(m0 + r) * DU + ku + q4];
                int kp = id >> 5, n4 = (id & 31) * 4;
                rb[j] = *(const uint4*)&W[(ku + kp) * 1024 + n0 + n4];
            }
        }
        __syncthreads();
    }

    // ---- epilogue ----
    if (mode == 0) {
        uint32_t* Yh = (z == 0) ? Yh0 : (z == 1) ? Yh1 : Yh2;
        const float sc = (z == 0) ? 0.125f : 1.0f;   // fold 1/sqrt(dh) into Q
#pragma unroll
        for (int am = 0; am < 2; am++) {
            int r0 = m0 + wm * 32 + am * 16 + g;
#pragma unroll
            for (int n = 0; n < 8; n++) {
                int cu = (n0 + wn * 64 + n * 8 + 2 * t4) >> 1;
                Yh[(r0)     * DU + cu] = ph2(acc[am][n][0] * sc, acc[am][n][1] * sc);
                Yh[(r0 + 8) * DU + cu] = ph2(acc[am][n][2] * sc, acc[am][n][3] * sc);
            }
        }
    } else {
#pragma unroll
        for (int am = 0; am < 2; am++) {
            int r0 = m0 + wm * 32 + am * 16 + g;
#pragma unroll
            for (int n = 0; n < 8; n++) {
                int c = n0 + wn * 64 + n * 8 + 2 * t4;
                *(float2*)&Yf[(r0)     * 1024 + c] =
                    make_float2(acc[am][n][0], acc[am][n][1]);
                *(float2*)&Yf[(r0 + 8) * 1024 + c] =
                    make_float2(acc[am][n][2], acc[am][n][3]);
            }
        }
    }
}

// ---------------- Flash attention (fp16 MMA, causal + pad mask) ------------
// Block = (q-tile 128, head, batch). 128 threads = 4 warps; warp w owns query
// rows w*32..w*32+31 as two m16 sub-tiles. q/k/v/ctx all fp16 in gmem.
#define BRF 128
#define BCF 64
#define LDQ2 36   // Qs/Ks/Ps pair-stride (4g+t4 conflict-free: 36%8==4)
#define LDV2 72   // Vs pair-row stride  (8t4+g conflict-free: 72%32==8)
#define FQ_OFF 0
#define FK_OFF (128 * LDQ2)                // 4608
#define FP_OFF (FK_OFF + 64 * LDQ2)       // 6912
#define FV_OFF (FP_OFF + 128 * LDQ2)      // 11520
#define FM_OFF (FV_OFF + 32 * LDV2)       // 13824
#define FSMEM_U32 (FM_OFF + 64)           // 13888 -> 55552 bytes

__global__ __launch_bounds__(128, 3)
void flash_f16(const uint32_t* __restrict__ q, const uint32_t* __restrict__ k,
               const uint32_t* __restrict__ v, const int* __restrict__ kini,
               uint32_t* __restrict__ ctx) {
    extern __shared__ uint32_t smu[];
    uint32_t* Qs = smu + FQ_OFF;
    uint32_t* Ks = smu + FK_OFF;
    uint32_t* Ps = smu + FP_OFF;
    uint32_t* Vs = smu + FV_OFF;
    float* pmask = (float*)(smu + FM_OFF);

    const int tid = threadIdx.x;
    const int lane = tid & 31;
    const int w = tid >> 5;
    const int g = lane >> 2, t4 = lane & 3;
    const int qt = (int)gridDim.x - 1 - (int)blockIdx.x;  // heavy tiles first
    const int h = blockIdx.y, b = blockIdx.z;
    const int q0 = qt * BRF;
    const int rowbase = b * S_;
    const int hoffu = h * (DH_ / 2);   // head offset in u32 units

    // Load Q tile 128x64 halves (already pre-scaled by 0.125 in projection)
#pragma unroll
    for (int i = 0; i < 8; i++) {
        int idx = tid + i * 128;        // 0..1023 uint4 units
        int r = idx >> 3, c4 = (idx & 7) * 4;
        *(uint4*)&Qs[r * LDQ2 + c4] =
            *(const uint4*)&q[(rowbase + q0 + r) * DU + hoffu + c4];
    }

    float m_[2][2], l_[2][2];
    float o[2][8][4];
#pragma unroll
    for (int am = 0; am < 2; am++) {
        m_[am][0] = -1e30f; m_[am][1] = -1e30f;
        l_[am][0] = 0.f;    l_[am][1] = 0.f;
#pragma unroll
        for (int n = 0; n < 8; n++)
#pragma unroll
            for (int e = 0; e < 4; e++) o[am][n][e] = 0.f;
    }

    const int qb = w * 32;
    const int ktmax = 2 * qt + 1;

    for (int kt = 0; kt <= ktmax; kt++) {
        const int k0 = kt * BCF;
        __syncthreads();   // Ks/Vs/Ps safe to overwrite (orders Qs on kt=0)
        // K tile 64x64 halves: direct copy
#pragma unroll
        for (int i = 0; i < 4; i++) {
            int idx = tid + i * 128;    // 0..511 uint4 units
            int r = idx >> 3, c4 = (idx & 7) * 4;
            *(uint4*)&Ks[r * LDQ2 + c4] =
                *(const uint4*)&k[(rowbase + k0 + r) * DU + hoffu + c4];
        }
        // V tile: interleave adjacent key rows into half2 via prmt
#pragma unroll
        for (int i = 0; i < 4; i++) {
            int u = tid + i * 128;      // 0..511: 32 kp x 16 quad-cols
            int kp = u >> 4, gq4 = u & 15;
            uint2 pa = *(const uint2*)&v[(rowbase + k0 + 2 * kp)     * DU + hoffu + gq4 * 2];
            uint2 pb = *(const uint2*)&v[(rowbase + k0 + 2 * kp + 1) * DU + hoffu + gq4 * 2];
            int c4 = gq4 * 4;
            Vs[kp * LDV2 + c4 + 0] = __byte_perm(pa.x, pb.x, 0x5410);
            Vs[kp * LDV2 + c4 + 1] = __byte_perm(pa.x, pb.x, 0x7632);
            Vs[kp * LDV2 + c4 + 2] = __byte_perm(pa.y, pb.y, 0x5410);
            Vs[kp * LDV2 + c4 + 3] = __byte_perm(pa.y, pb.y, 0x7632);
        }
        if (tid < 64)
            pmask[tid] = (kini[rowbase + k0 + tid] != 0) ? 0.f : -1e10f;
        __syncthreads();

        // ---- S = Q @ K^T : 32 warp rows x 64 key cols (k16 x 4 steps) ----
        float s[2][8][4];
#pragma unroll
        for (int am = 0; am < 2; am++)
#pragma unroll
            for (int n = 0; n < 8; n++)
#pragma unroll
                for (int e = 0; e < 4; e++) s[am][n][e] = 0.f;
#pragma unroll
        for (int ks = 0; ks < 4; ks++) {
            const int kb = ks * 8;
            uint32_t a[2][4];
#pragma unroll
            for (int am = 0; am < 2; am++) {
                int rq = qb + am * 16;
                a[am][0] = Qs[(rq + g)     * LDQ2 + kb + t4];
                a[am][1] = Qs[(rq + g + 8) * LDQ2 + kb + t4];
                a[am][2] = Qs[(rq + g)     * LDQ2 + kb + t4 + 4];
                a[am][3] = Qs[(rq + g + 8) * LDQ2 + kb + t4 + 4];
            }
#pragma unroll
            for (int n = 0; n < 8; n++) {
                uint32_t b0 = Ks[(n * 8 + g) * LDQ2 + kb + t4];
                uint32_t b1 = Ks[(n * 8 + g) * LDQ2 + kb + t4 + 4];
                mma_f16(s[0][n], a[0], b0, b1);
                mma_f16(s[1][n], a[1], b0, b1);
            }
        }

        // ---- masks + online softmax per am block -------------------------
#pragma unroll
        for (int am = 0; am < 2; am++) {
            const int gq0 = q0 + qb + am * 16 + g;
            const int gq1 = gq0 + 8;
#pragma unroll
            for (int n = 0; n < 8; n++) {
                int c0 = n * 8 + 2 * t4;
#pragma unroll
                for (int e = 0; e < 2; e++) {
                    int gk = k0 + c0 + e;
                    float pm = pmask[c0 + e];
                    s[am][n][e]     += (gk > gq0) ? -1e10f : pm;
                    s[am][n][e + 2] += (gk > gq1) ? -1e10f : pm;
                }
            }
            float rm0 = -1e30f, rm1 = -1e30f;
#pragma unroll
            for (int n = 0; n < 8; n++) {
                rm0 = fmaxf(rm0, fmaxf(s[am][n][0], s[am][n][1]));
                rm1 = fmaxf(rm1, fmaxf(s[am][n][2], s[am][n][3]));
            }
#pragma unroll
            for (int msk = 1; msk < 4; msk <<= 1) {
                rm0 = fmaxf(rm0, __shfl_xor_sync(0xffffffffu, rm0, msk));
                rm1 = fmaxf(rm1, __shfl_xor_sync(0xffffffffu, rm1, msk));
            }
            float mn0 = fmaxf(m_[am][0], rm0), mn1 = fmaxf(m_[am][1], rm1);
            float rs0 = 0.f, rs1 = 0.f;
#pragma unroll
            for (int n = 0; n < 8; n++) {
                s[am][n][0] = __expf(s[am][n][0] - mn0);
                s[am][n][1] = __expf(s[am][n][1] - mn0);
                s[am][n][2] = __expf(s[am][n][2] - mn1);
                s[am][n][3] = __expf(s[am][n][3] - mn1);
                rs0 += s[am][n][0] + s[am][n][1];
                rs1 += s[am][n][2] + s[am][n][3];
            }
#pragma unroll
            for (int msk = 1; msk < 4; msk <<= 1) {
                rs0 += __shfl_xor_sync(0xffffffffu, rs0, msk);
                rs1 += __shfl_xor_sync(0xffffffffu, rs1, msk);
            }
            float c0s = __expf(m_[am][0] - mn0), c1s = __expf(m_[am][1] - mn1);
            l_[am][0] = l_[am][0] * c0s + rs0; m_[am][0] = mn0;
            l_[am][1] = l_[am][1] * c1s + rs1; m_[am][1] = mn1;
#pragma unroll
            for (int n = 0; n < 8; n++) {
                o[am][n][0] *= c0s; o[am][n][1] *= c0s;
                o[am][n][2] *= c1s; o[am][n][3] *= c1s;
            }

            // stage P as fp16 pairs (cols 2t4,2t4+1 pack into one half2)
            const int rq = qb + am * 16;
#pragma unroll
            for (int n = 0; n < 8; n++) {
                Ps[(rq + g)     * LDQ2 + n * 4 + t4] = ph2(s[am][n][0], s[am][n][1]);
                Ps[(rq + g + 8) * LDQ2 + n * 4 + t4] = ph2(s[am][n][2], s[am][n][3]);
            }
        }
        __syncwarp();

        // ---- O += P @ V (k16 x 4 steps over 64 keys) ---------------------
#pragma unroll
        for (int ks = 0; ks < 4; ks++) {
            const int kb = ks * 8;
            uint32_t a[2][4];
#pragma unroll
            for (int am = 0; am < 2; am++) {
                int rq = qb + am * 16;
                a[am][0] = Ps[(rq + g)     * LDQ2 + kb + t4];
                a[am][1] = Ps[(rq + g + 8) * LDQ2 + kb + t4];
                a[am][2] = Ps[(rq + g)     * LDQ2 + kb + t4 + 4];
                a[am][3] = Ps[(rq + g + 8) * LDQ2 + kb + t4 + 4];
            }
#pragma unroll
            for (int n = 0; n < 8; n++) {
                uint32_t b0 = Vs[(kb + t4)     * LDV2 + n * 8 + g];
                uint32_t b1 = Vs[(kb + t4 + 4) * LDV2 + n * 8 + g];
                mma_f16(o[0][n], a[0], b0, b1);
                mma_f16(o[1][n], a[1], b0, b1);
            }
        }
        __syncwarp();  // Ps reads done before next iteration overwrites
    }

    // epilogue: normalize, store ctx (fp16) — head slice at hoffu
#pragma unroll
    for (int am = 0; am < 2; am++) {
        float inv0 = 1.f / l_[am][0], inv1 = 1.f / l_[am][1];
        const int r0 = rowbase + q0 + qb + am * 16 + g;
#pragma unroll
        for (int n = 0; n < 8; n++) {
            int cu = hoffu + n * 4 + t4;
            ctx[(r0)     * DU + cu] = ph2(o[am][n][0] * inv0, o[am][n][1] * inv0);
            ctx[(r0 + 8) * DU + cu] = ph2(o[am][n][2] * inv1, o[am][n][3] * inv1);
        }
    }
}

// ---------------- launch -----------------------------------------------------
extern "C" void kernel_launch(void* const* d_in, const int* in_sizes, int n_in,
                              void* d_out, int out_size) {
    const float* Q_emb = (const float*)d_in[0];
    const float* K_emb = (const float*)d_in[1];
    const float* V_emb = (const float*)d_in[2];
    // d_in[3] = Q_ini (unused by reference math)
    const int*   K_ini = (const int*)d_in[4];
    const float* WQ = (const float*)d_in[5];
    const float* WK = (const float*)d_in[6];
    const float* WV = (const float*)d_in[7];
    const float* WO = (const float*)d_in[8];
    float* out = (float*)d_out;

    uint32_t *gq, *gk, *gv, *gctx, *gxh, *gwp;
    cudaGetSymbolAddress((void**)&gq,   g_q);
    cudaGetSymbolAddress((void**)&gk,   g_k);
    cudaGetSymbolAddress((void**)&gv,   g_v);
    cudaGetSymbolAddress((void**)&gctx, g_ctx);
    cudaGetSymbolAddress((void**)&gxh,  g_xh);
    cudaGetSymbolAddress((void**)&gwp,  g_wp);

    const int smem_flash = FSMEM_U32 * (int)sizeof(uint32_t);  // ~55.6 KB
    cudaFuncSetAttribute(flash_f16, cudaFuncAttributeMaxDynamicSharedMemorySize,
                         smem_flash);

    // pre-passes: fp16 conversion + weight packing
    conv_h<<<dim3(M_ * DU / 1024, 1, 3), 256>>>(Q_emb, K_emb, V_emb, gxh);
    pack_w<<<dim3(512, 1, 4), 256>>>(WQ, WK, WV, WO, gwp);

    // fused QKV projections (fp16 out, Q pre-scaled by 0.125)
    gemm_f16<<<dim3(8, 64, 3), 256>>>(gxh, gwp, gq, gk, gv, nullptr, 0);

    dim3 fgrid(S_ / BRF, H_, B_);  // (16, 16, 4)
    flash_f16<<<fgrid, 128, smem_flash>>>(gq, gk, gv, K_ini, gctx);

    // output projection: ctx(fp16) @ WO -> fp32 out
    gemm_f16<<<dim3(8, 64, 1), 256>>>(gctx, gwp + (size_t)3 * 512 * 1024,
                                      nullptr, nullptr, nullptr, out, 1);
}